// round 10
// baseline (speedup 1.0000x reference)
#include <cuda_runtime.h>
#include <cuda.h>
#include <cstdint>

// ===========================================================================
#define BATCH 16
#define SEQ   1024
#define DT    1024
#define HID   512
#define NEG_INF_F (-1.0e9f)
static __device__ __host__ constexpr float INV_SQRT = 0.03125f;

static constexpr long ELEM1 = 16LL * 1024 * 1024;
__device__ __align__(1024) float g_scr[ELEM1 * 10 + 6L * DT * DT + 400000];

// ===========================================================================
// PTX helpers
// ===========================================================================
__device__ __forceinline__ uint32_t smem_u32(const void* p) {
    uint32_t a;
    asm("{ .reg .u64 t; cvta.to.shared.u64 t, %1; cvt.u32.u64 %0, t; }" : "=r"(a) : "l"(p));
    return a;
}
__device__ __forceinline__ uint32_t lds_u(uint32_t a) {
    uint32_t v;
    asm volatile("ld.shared.b32 %0, [%1];" : "=r"(v) : "r"(a));
    return v;
}
__device__ __forceinline__ float rnd_tf32(float f) {
    uint32_t r;
    asm volatile("cvt.rna.tf32.f32 %0, %1;" : "=r"(r) : "f"(f));
    return __uint_as_float(r);
}

#define MBARRIER_INIT(mbar, count) \
    asm volatile("mbarrier.init.shared.b64 [%0], %1;" :: "r"((uint32_t)(mbar)), "r"((uint32_t)(count)) : "memory")
#define MBARRIER_EXPECT_TX(mbar, bytes) \
    asm volatile("mbarrier.arrive.expect_tx.shared.b64 _, [%0], %1;" \
        :: "r"((uint32_t)(mbar)), "r"((uint32_t)(bytes)) : "memory")
#define MBARRIER_ARRIVE(mbar) \
    asm volatile("mbarrier.arrive.release.cta.shared.b64 _, [%0];" :: "r"((uint32_t)(mbar)) : "memory")
#define MBARRIER_WAIT_PARITY(mbar, parity) do {                                  \
    uint32_t _m = (uint32_t)(mbar);  uint32_t _p = (uint32_t)(parity);           \
    asm volatile(                                                                 \
        "{\n\t.reg .pred P1;\n\t"                                                 \
        "WL_%=:\n\t"                                                              \
        "mbarrier.try_wait.parity.acquire.cta.shared::cta.b64 P1, [%0], %1, 0x989680;\n\t" \
        "@P1 bra.uni WD_%=;\n\t"                                                  \
        "bra.uni WL_%=;\n\t"                                                      \
        "WD_%=:\n\t}"                                                             \
        :: "r"(_m), "r"(_p) : "memory");                                          \
} while (0)
#define TMA_LOAD_3D(saddr, tmap, cx, cy, cz, mbar) \
    asm volatile( \
        "cp.async.bulk.tensor.3d.shared::cta.global.tile.mbarrier::complete_tx::bytes " \
        "[%0], [%1, {%2, %3, %4}], [%5];" \
        :: "r"((uint32_t)(saddr)), "l"(tmap), "r"((int)(cx)), "r"((int)(cy)), "r"((int)(cz)), \
           "r"((uint32_t)(mbar)) : "memory")

// ===========================================================================
// GEMM config: CTA 128x128, KT=32/stage, 3 stages.
// 160 threads: warps 0-3 consumers (64x64 tiles), warp 4 = TMA producer.
// ===========================================================================
static constexpr int BM = 128, BN = 128, KT = 32, STAGES = 3;
static constexpr int ABYT = BM * KT * 4;
static constexpr int BBYT = BN * KT * 4;
static constexpr int STB  = ABYT + BBYT;
static constexpr int SMEM_DYN = 1024 + STAGES * STB;   // 99328
static constexpr int NTHR  = 160;   // launch size
static constexpr int NTHRC = 128;   // consumer threads (epilogue workers)

// Producer/consumer mainloop. acc must be declared by caller.
#define GEMM_PIPE(tmA_, tmB_, zA_, zB_)                                             \
    if (tid == 0) {                                                                 \
        for (int s_ = 0; s_ < STAGES; s_++) {                                       \
            MBARRIER_INIT(FULLB(s_), 1);                                            \
            MBARRIER_INIT(EMPTYB(s_), 4);                                           \
        }                                                                           \
    }                                                                               \
    __syncthreads();                                                                \
    if (warp == 4) {                                                                \
        if (lane == 0) {                                                            \
            int ps = 0;                                                             \
            for (int kt = 0; kt < 32; kt++) {                                       \
                if (kt >= STAGES)                                                   \
                    MBARRIER_WAIT_PARITY(EMPTYB(ps), ((kt - STAGES) / 3) & 1);      \
                MBARRIER_EXPECT_TX(FULLB(ps), STB);                                 \
                TMA_LOAD_3D(sb + ps * STB,        &(tmA_), kt * KT, m0, (zA_), FULLB(ps)); \
                TMA_LOAD_3D(sb + ps * STB + ABYT, &(tmB_), kt * KT, n0, (zB_), FULLB(ps)); \
                if (++ps == STAGES) ps = 0;                                         \
            }                                                                       \
        }                                                                           \
    } else {                                                                        \
        const uint32_t gx   = (uint32_t)gID << 4;                                   \
        const uint32_t rowA = (uint32_t)(wm * 64 + gID) * 128;                      \
        const uint32_t rowB = (uint32_t)(wn * 64 + gID) * 128;                      \
        int s = 0, ph = 0;                                                          \
        for (int kt = 0; kt < 32; kt++) {                                           \
            const uint32_t stg = sb + s * STB;                                      \
            MBARRIER_WAIT_PARITY(FULLB(s), ph);                                     \
            const uint32_t aBase = stg + rowA;                                      \
            const uint32_t bBase = stg + ABYT + rowB;                               \
            _Pragma("unroll")                                                       \
            for (int kk = 0; kk < 4; kk++) {                                        \
                const uint32_t off0 = ((uint32_t)(kk * 32 + tig * 4)) ^ gx;         \
                const uint32_t off1 = off0 ^ 16u;                                   \
                uint32_t ua[4][4], ub[8][2];                                        \
                _Pragma("unroll")                                                   \
                for (int mi = 0; mi < 4; mi++) {                                    \
                    ua[mi][0] = lds_u(aBase + mi * 2048 + off0);                    \
                    ua[mi][1] = lds_u(aBase + mi * 2048 + 1024 + off0);             \
                    ua[mi][2] = lds_u(aBase + mi * 2048 + off1);                    \
                    ua[mi][3] = lds_u(aBase + mi * 2048 + 1024 + off1);             \
                }                                                                   \
                _Pragma("unroll")                                                   \
                for (int ni = 0; ni < 8; ni++) {                                    \
                    ub[ni][0] = lds_u(bBase + ni * 1024 + off0);                    \
                    ub[ni][1] = lds_u(bBase + ni * 1024 + off1);                    \
                }                                                                   \
                _Pragma("unroll")                                                   \
                for (int mi = 0; mi < 4; mi++)                                      \
                    _Pragma("unroll")                                               \
                    for (int ni = 0; ni < 8; ni++)                                  \
                        asm volatile(                                               \
                            "mma.sync.aligned.m16n8k8.row.col.f32.tf32.tf32.f32 "   \
                            "{%0,%1,%2,%3},{%4,%5,%6,%7},{%8,%9},{%0,%1,%2,%3};"    \
                            : "+f"(acc[mi][ni][0]), "+f"(acc[mi][ni][1]),           \
                              "+f"(acc[mi][ni][2]), "+f"(acc[mi][ni][3])            \
                            : "r"(ua[mi][0]), "r"(ua[mi][1]), "r"(ua[mi][2]), "r"(ua[mi][3]), \
                              "r"(ub[ni][0]), "r"(ub[ni][1]));                      \
            }                                                                       \
            __syncwarp();                                                           \
            if (lane == 0) MBARRIER_ARRIVE(EMPTYB(s));                              \
            if (++s == STAGES) { s = 0; ph ^= 1; }                                  \
        }                                                                           \
    }                                                                               \
    __syncthreads();

// ===========================================================================
// Batched GEMM (no bias): C[z][M,N] = A[z] @ B[z]^T
// ===========================================================================
__global__ void __launch_bounds__(NTHR, 2)
gemm_tc(const __grid_constant__ CUtensorMap tmA,
        const __grid_constant__ CUtensorMap tmB,
        float* __restrict__ C, long sCz)
{
    extern __shared__ char dynraw[];
    __shared__ __align__(8) unsigned long long mb[2 * STAGES];
    uint32_t d0 = smem_u32(dynraw);
    uint32_t sb = (d0 + 1023u) & ~1023u;
    const int tid = threadIdx.x;
    const int warp = tid >> 5, lane = tid & 31;
    const int wm = warp & 1, wn = (warp >> 1) & 1;
    const int gID = lane >> 2, tig = lane & 3;
    const int m0 = blockIdx.y * BM, n0 = blockIdx.x * BN, z = blockIdx.z;
    const uint32_t mbase = smem_u32(mb);
#define FULLB(s)  (mbase + 8 * (s))
#define EMPTYB(s) (mbase + 24 + 8 * (s))

    float acc[4][8][4];
#pragma unroll
    for (int mi = 0; mi < 4; mi++)
#pragma unroll
        for (int ni = 0; ni < 8; ni++)
#pragma unroll
            for (int e = 0; e < 4; e++) acc[mi][ni][e] = 0.0f;

    GEMM_PIPE(tmA, tmB, z, z)

    float* ep = (float*)(dynraw + (sb - d0));
    const int P = 132;
    if (warp < 4) {
#pragma unroll
        for (int mi = 0; mi < 4; mi++)
#pragma unroll
            for (int ni = 0; ni < 8; ni++) {
                const int r = wm * 64 + mi * 16 + gID;
                const int c = wn * 64 + ni * 8 + 2 * tig;
                *(float2*)(ep + r * P + c)       = make_float2(acc[mi][ni][0], acc[mi][ni][1]);
                *(float2*)(ep + (r + 8) * P + c) = make_float2(acc[mi][ni][2], acc[mi][ni][3]);
            }
    }
    __syncthreads();
    float* Cz = C + (long)z * sCz;
    if (tid < NTHRC) {
#pragma unroll
        for (int it = 0; it < 32; it++) {
            const int idx = tid + it * NTHRC;
            const int r = idx >> 5, c4 = (idx & 31) * 4;
            float4 v = *(float4*)(ep + r * P + c4);
            *(float4*)(Cz + (long)(m0 + r) * 1024 + n0 + c4) = v;
        }
    }
#undef FULLB
#undef EMPTYB
}

// ===========================================================================
// Wide projection GEMM: C[M, 3072] = A[M,1024] @ W[3072,1024]^T + biasC
// ===========================================================================
__global__ void __launch_bounds__(NTHR, 2)
gemm_proj(const __grid_constant__ CUtensorMap tmA,
          const __grid_constant__ CUtensorMap tmB,
          float* __restrict__ p0, float* __restrict__ p1, float* __restrict__ p2,
          const float* __restrict__ biasC, uint32_t trans_mask)
{
    extern __shared__ char dynraw[];
    __shared__ __align__(8) unsigned long long mb[2 * STAGES];
    uint32_t d0 = smem_u32(dynraw);
    uint32_t sb = (d0 + 1023u) & ~1023u;
    const int tid = threadIdx.x;
    const int warp = tid >> 5, lane = tid & 31;
    const int wm = warp & 1, wn = (warp >> 1) & 1;
    const int gID = lane >> 2, tig = lane & 3;
    const int m0 = blockIdx.y * BM, n0 = blockIdx.x * BN;
    const uint32_t mbase = smem_u32(mb);
#define FULLB(s)  (mbase + 8 * (s))
#define EMPTYB(s) (mbase + 24 + 8 * (s))

    float acc[4][8][4];
#pragma unroll
    for (int mi = 0; mi < 4; mi++)
#pragma unroll
        for (int ni = 0; ni < 8; ni++)
#pragma unroll
            for (int e = 0; e < 4; e++) acc[mi][ni][e] = 0.0f;

    GEMM_PIPE(tmA, tmB, 0, 0)

    const int sec = n0 >> 10;
    const int n0l = n0 & 1023;
    float* dst = (sec == 0) ? p0 : (sec == 1) ? p1 : p2;
    const bool tr = (trans_mask >> sec) & 1u;
    float* ep = (float*)(dynraw + (sb - d0));

    if (warp < 4) {
        // bias + round
#pragma unroll
        for (int ni = 0; ni < 8; ni++) {
            const int nc = n0 + wn * 64 + ni * 8 + 2 * tig;
            const float b0 = __ldg(biasC + nc), b1 = __ldg(biasC + nc + 1);
#pragma unroll
            for (int mi = 0; mi < 4; mi++) {
                acc[mi][ni][0] = rnd_tf32(acc[mi][ni][0] + b0);
                acc[mi][ni][1] = rnd_tf32(acc[mi][ni][1] + b1);
                acc[mi][ni][2] = rnd_tf32(acc[mi][ni][2] + b0);
                acc[mi][ni][3] = rnd_tf32(acc[mi][ni][3] + b1);
            }
        }
        if (!tr) {
            const int P = 132;
#pragma unroll
            for (int mi = 0; mi < 4; mi++)
#pragma unroll
                for (int ni = 0; ni < 8; ni++) {
                    const int r = wm * 64 + mi * 16 + gID;
                    const int c = wn * 64 + ni * 8 + 2 * tig;
                    *(float2*)(ep + r * P + c)       = make_float2(acc[mi][ni][0], acc[mi][ni][1]);
                    *(float2*)(ep + (r + 8) * P + c) = make_float2(acc[mi][ni][2], acc[mi][ni][3]);
                }
        } else {
            const int P = 129;
#pragma unroll
            for (int mi = 0; mi < 4; mi++)
#pragma unroll
                for (int ni = 0; ni < 8; ni++) {
                    const int r = wm * 64 + mi * 16 + gID;
                    const int c = wn * 64 + ni * 8 + 2 * tig;
                    ep[r * P + c]           = acc[mi][ni][0];
                    ep[r * P + c + 1]       = acc[mi][ni][1];
                    ep[(r + 8) * P + c]     = acc[mi][ni][2];
                    ep[(r + 8) * P + c + 1] = acc[mi][ni][3];
                }
        }
    }
    __syncthreads();
    if (tid < NTHRC) {
        if (!tr) {
            const int P = 132;
#pragma unroll
            for (int it = 0; it < 32; it++) {
                const int idx = tid + it * NTHRC;
                const int r = idx >> 5, c4 = (idx & 31) * 4;
                float4 v = *(float4*)(ep + r * P + c4);
                *(float4*)(dst + (long)(m0 + r) * 1024 + n0l + c4) = v;
            }
        } else {
            const int P = 129;
            const int b   = m0 >> 10;
            const int mlb = m0 & 1023;
#pragma unroll 8
            for (int it = 0; it < 128; it++) {
                const int idx = tid + it * NTHRC;
                const int n = idx >> 7, m = idx & 127;
                dst[((long)b << 20) + (long)(n0l + n) * 1024 + (mlb + m)] = ep[m * P + n];
            }
        }
    }
#undef FULLB
#undef EMPTYB
}

// ===========================================================================
// Pre-round to tf32
// ===========================================================================
__global__ void round_kernel(const float4* __restrict__ in, float4* __restrict__ out, long n4)
{
    long i = (long)blockIdx.x * blockDim.x + threadIdx.x;
    long stride = (long)gridDim.x * blockDim.x;
    for (; i < n4; i += stride) {
        float4 v = in[i];
        v.x = rnd_tf32(v.x); v.y = rnd_tf32(v.y);
        v.z = rnd_tf32(v.z); v.w = rnd_tf32(v.w);
        out[i] = v;
    }
}

struct Ptr6 { const float4* in[6]; };
__global__ void round6_kernel(Ptr6 p, float4* __restrict__ out, long n4each)
{
    const float4* in = p.in[blockIdx.y];
    float4* o = out + blockIdx.y * n4each;
    long i = (long)blockIdx.x * blockDim.x + threadIdx.x;
    long stride = (long)gridDim.x * blockDim.x;
    for (; i < n4each; i += stride) {
        float4 v = in[i];
        v.x = rnd_tf32(v.x); v.y = rnd_tf32(v.y);
        v.z = rnd_tf32(v.z); v.w = rnd_tf32(v.w);
        o[i] = v;
    }
}

__global__ void cat_bias(const float* __restrict__ a, const float* __restrict__ b,
                         const float* __restrict__ c, float* __restrict__ o)
{
    int i = blockIdx.x * 256 + threadIdx.x;
    o[i] = (i < 1024) ? a[i] : (i < 2048) ? b[i - 1024] : c[i - 2048];
}

// ===========================================================================
// Two-stage mean pool
// ===========================================================================
__global__ void pool1_kernel(const float* __restrict__ src, float* __restrict__ part)
{
    int b = blockIdx.y, sp = blockIdx.z;
    int d = blockIdx.x * 256 + threadIdx.x;
    const float* p = src + ((long)b << 20) + ((long)sp << 17) + d;
    float s = 0.f;
#pragma unroll 16
    for (int m = 0; m < 128; m++) s += p[m << 10];
    part[(((b << 3) + sp) << 10) + d] = s;
}
__global__ void pool2_kernel(const float* __restrict__ part, float* __restrict__ dst)
{
    int b = blockIdx.y;
    int d = blockIdx.x * 256 + threadIdx.x;
    float s = 0.f;
#pragma unroll
    for (int sp = 0; sp < 8; sp++) s += part[(((b << 3) + sp) << 10) + d];
    dst[(b << 10) + d] = s * (1.0f / 1024.0f);
}

// ===========================================================================
// Gate FFN + mask/softmax/transpose
// ===========================================================================
__global__ void ffn_kernel(const float* __restrict__ poolV, const float* __restrict__ poolT,
                           const float* __restrict__ w1, const float* __restrict__ b1,
                           const float* __restrict__ w2, const float* __restrict__ b2,
                           float* __restrict__ lout)
{
    __shared__ float x[2 * DT];
    __shared__ float red[HID];
    int b = blockIdx.x, t = threadIdx.x;
    for (int i = t; i < 2 * DT; i += HID)
        x[i] = (i < DT) ? poolV[b * DT + i] : poolT[b * DT + (i - DT)];
    __syncthreads();
    float acc = b1[t];
    const float* wr = w1 + (long)t * (2 * DT);
#pragma unroll 8
    for (int k = 0; k < 2 * DT; k++) acc += wr[k] * x[k];
    float h = fmaxf(acc, 0.0f);
    red[t] = h * w2[t];
    __syncthreads();
    for (int s = HID / 2; s > 0; s >>= 1) {
        if (t < s) red[t] += red[t + s];
        __syncthreads();
    }
    if (t == 0) lout[b] = 1.0f / (1.0f + expf(-(red[0] + b2[0])));
}

__device__ __forceinline__ float block_max(float v, float* red)
{
    int t = threadIdx.x;
    red[t] = v; __syncthreads();
    for (int s = 128; s > 0; s >>= 1) {
        if (t < s) red[t] = fmaxf(red[t], red[t + s]);
        __syncthreads();
    }
    float r = red[0]; __syncthreads();
    return r;
}
__device__ __forceinline__ float block_sum(float v, float* red)
{
    int t = threadIdx.x;
    red[t] = v; __syncthreads();
    for (int s = 128; s > 0; s >>= 1) {
        if (t < s) red[t] += red[t + s];
        __syncthreads();
    }
    float r = red[0]; __syncthreads();
    return r;
}

__global__ void mask_kernel(const float* __restrict__ S, const float* __restrict__ lv,
                            float* __restrict__ maskO)
{
    __shared__ float red[256];
    int t = threadIdx.x;
    long row = (long)blockIdx.y * SEQ + blockIdx.x;
    const float* p = S + row * SEQ;
    float x[4];
    float mx = -3.4e38f;
#pragma unroll
    for (int i = 0; i < 4; i++) {
        x[i] = p[t + i * 256] * INV_SQRT;
        mx = fmaxf(mx, x[i]);
    }
    mx = block_max(mx, red);
    float s = 0.f;
#pragma unroll
    for (int i = 0; i < 4; i++) s += expf(x[i] - mx);
    s = block_sum(s, red);
    float l = lv[blockIdx.y];
    float* o = maskO + row * SEQ;
#pragma unroll
    for (int i = 0; i < 4; i++)
        o[t + i * 256] = ((expf(x[i] - mx) / s) >= l) ? 1.0f : 0.0f;
}

__global__ void msoftmax_kernel(float* __restrict__ S, const float* __restrict__ maskM)
{
    __shared__ float red[256];
    int t = threadIdx.x;
    long row = (long)blockIdx.y * SEQ + blockIdx.x;
    float* p = S + row * SEQ;
    const float* mk = maskM + row * SEQ;
    float x[4];
    float mx = -3.4e38f;
#pragma unroll
    for (int i = 0; i < 4; i++) {
        int idx = t + i * 256;
        x[i] = (mk[idx] != 0.0f) ? p[idx] * INV_SQRT : NEG_INF_F;
        mx = fmaxf(mx, x[i]);
    }
    mx = block_max(mx, red);
    float s = 0.f;
#pragma unroll
    for (int i = 0; i < 4; i++) s += expf(x[i] - mx);
    s = block_sum(s, red);
#pragma unroll
    for (int i = 0; i < 4; i++)
        p[t + i * 256] = rnd_tf32(expf(x[i] - mx) / s);
}

__global__ void transpose_kernel(const float* __restrict__ in, float* __restrict__ out)
{
    __shared__ float tile[32][33];
    long base = (long)blockIdx.z << 20;
    int m = blockIdx.y * 32 + threadIdx.y;
    int n = blockIdx.x * 32 + threadIdx.x;
    tile[threadIdx.y][threadIdx.x] = in[base + (long)m * SEQ + n];
    __syncthreads();
    int n2 = blockIdx.x * 32 + threadIdx.y;
    int m2 = blockIdx.y * 32 + threadIdx.x;
    out[base + (long)n2 * SEQ + m2] = tile[threadIdx.x][threadIdx.y];
}

// ===========================================================================
// Host side
// ===========================================================================
typedef CUresult (*PFN_encodeTiled)(CUtensorMap*, CUtensorMapDataType, cuuint32_t, void*,
                                    const cuuint64_t*, const cuuint64_t*, const cuuint32_t*,
                                    const cuuint32_t*, CUtensorMapInterleave, CUtensorMapSwizzle,
                                    CUtensorMapL2promotion, CUtensorMapFloatOOBfill);
static PFN_encodeTiled g_enc = nullptr;

static void enc3d(CUtensorMap* tm, const void* p, long K, long R, long Z)
{
    cuuint64_t dims[3] = {(cuuint64_t)K, (cuuint64_t)R, (cuuint64_t)Z};
    cuuint64_t str[2]  = {(cuuint64_t)(K * 4), (cuuint64_t)(K * R * 4)};
    cuuint32_t box[3]  = {(cuuint32_t)KT, 128, 1};
    cuuint32_t es[3]   = {1, 1, 1};
    g_enc(tm, CU_TENSOR_MAP_DATA_TYPE_FLOAT32, 3, (void*)p, dims, str, box, es,
          CU_TENSOR_MAP_INTERLEAVE_NONE, CU_TENSOR_MAP_SWIZZLE_128B,
          CU_TENSOR_MAP_L2_PROMOTION_L2_128B, CU_TENSOR_MAP_FLOAT_OOB_FILL_NONE);
}

extern "C" void kernel_launch(void* const* d_in, const int* in_sizes, int n_in,
                              void* d_out, int out_size)
{
    (void)in_sizes; (void)n_in; (void)out_size;

    const float* oV     = (const float*)d_in[0];
    const float* oT     = (const float*)d_in[1];
    const float* Wq_v_w = (const float*)d_in[2];
    const float* Wq_v_b = (const float*)d_in[3];
    const float* Wk_t_w = (const float*)d_in[4];
    const float* Wk_t_b = (const float*)d_in[5];
    const float* Wv_t_w = (const float*)d_in[6];
    const float* Wv_t_b = (const float*)d_in[7];
    const float* Wq_t_w = (const float*)d_in[8];
    const float* Wq_t_b = (const float*)d_in[9];
    const float* Wk_v_w = (const float*)d_in[10];
    const float* Wk_v_b = (const float*)d_in[11];
    const float* Wv_v_w = (const float*)d_in[12];
    const float* Wv_v_b = (const float*)d_in[13];
    const float* ffn1_w = (const float*)d_in[14];
    const float* ffn1_b = (const float*)d_in[15];
    const float* ffn2_w = (const float*)d_in[16];
    const float* ffn2_b = (const float*)d_in[17];

    float* out_vt = (float*)d_out;
    float* out_tv = out_vt + ELEM1;
    float* maskO  = out_vt + 2 * ELEM1;

    static float* scr = nullptr;
    if (!scr) cudaGetSymbolAddress((void**)&scr, g_scr);
    if (!g_enc) {
        void* p = nullptr;
        cudaDriverEntryPointQueryResult st;
        cudaGetDriverEntryPoint("cuTensorMapEncodeTiled", &p, cudaEnableDefault, &st);
        g_enc = (PFN_encodeTiled)p;
    }
    static bool attr_done = false;
    if (!attr_done) {
        cudaFuncSetAttribute(gemm_tc,   cudaFuncAttributeMaxDynamicSharedMemorySize, SMEM_DYN);
        cudaFuncSetAttribute(gemm_proj, cudaFuncAttributeMaxDynamicSharedMemorySize, SMEM_DYN);
        attr_done = true;
    }

    float* Qv    = scr + 0 * ELEM1;
    float* Kt    = scr + 1 * ELEM1;
    float* VtT   = scr + 2 * ELEM1;   // (B, DT, SEQ)
    float* Qt    = scr + 3 * ELEM1;
    float* Kv    = scr + 4 * ELEM1;
    float* VvT   = scr + 5 * ELEM1;   // (B, DT, SEQ)
    float* Ssc   = scr + 6 * ELEM1;
    float* maskT = scr + 7 * ELEM1;
    float* oVr   = scr + 8 * ELEM1;
    float* oTr   = scr + 9 * ELEM1;
    float* Wr    = scr + 10 * ELEM1;
    float* poolV = Wr + 6L * DT * DT;
    float* poolT = poolV + BATCH * DT;
    float* lv    = poolT + BATCH * DT;
    float* partV = lv + 64;
    float* partT = partV + 8 * BATCH * 1024;
    float* biasV = partT + 8 * BATCH * 1024;
    float* biasT = biasV + 3072;

    // 0) pre-round GEMM inputs
    const long N4BIG = ELEM1 / 4;
    round_kernel<<<2048, 256>>>((const float4*)oV, (float4*)oVr, N4BIG);
    round_kernel<<<2048, 256>>>((const float4*)oT, (float4*)oTr, N4BIG);
    Ptr6 wp;
    wp.in[0] = (const float4*)Wq_v_w;  wp.in[1] = (const float4*)Wk_v_w;
    wp.in[2] = (const float4*)Wv_v_w;  wp.in[3] = (const float4*)Wk_t_w;
    wp.in[4] = (const float4*)Wv_t_w;  wp.in[5] = (const float4*)Wq_t_w;
    round6_kernel<<<dim3(256, 6), 256>>>(wp, (float4*)Wr, (long)DT * DT / 4);
    cat_bias<<<12, 256>>>(Wq_v_b, Wk_v_b, Wv_v_b, biasV);
    cat_bias<<<12, 256>>>(Wk_t_b, Wv_t_b, Wq_t_b, biasT);

    // 1) pools + gate
    pool1_kernel<<<dim3(4, BATCH, 8), 256>>>(oV, partV);
    pool1_kernel<<<dim3(4, BATCH, 8), 256>>>(oT, partT);
    pool2_kernel<<<dim3(4, BATCH), 256>>>(partV, poolV);
    pool2_kernel<<<dim3(4, BATCH), 256>>>(partT, poolT);
    ffn_kernel<<<BATCH, HID>>>(poolV, poolT, ffn1_w, ffn1_b, ffn2_w, ffn2_b, lv);

    CUtensorMap tA, tB;
    const dim3 gw(24, 128, 1);
    const dim3 gb(8, 8, BATCH);

    // 2) projections: 2 wide GEMMs
    enc3d(&tA, oVr, DT, BATCH * SEQ, 1);
    enc3d(&tB, Wr, DT, 3 * DT, 1);
    gemm_proj<<<gw, NTHR, SMEM_DYN>>>(tA, tB, Qv, Kv, VvT, biasV, 0b100u);

    enc3d(&tA, oTr, DT, BATCH * SEQ, 1);
    enc3d(&tB, Wr + 3L * DT * DT, DT, 3 * DT, 1);
    gemm_proj<<<gw, NTHR, SMEM_DYN>>>(tA, tB, Kt, VtT, Qt, biasT, 0b010u);

    const long S1 = (long)SEQ * SEQ;

    // 3) sim -> mask -> maskT
    enc3d(&tA, oVr, DT, SEQ, BATCH);
    enc3d(&tB, oTr, DT, SEQ, BATCH);
    gemm_tc<<<gb, NTHR, SMEM_DYN>>>(tA, tB, Ssc, S1);
    mask_kernel<<<dim3(SEQ, BATCH), 256>>>(Ssc, lv, maskO);
    transpose_kernel<<<dim3(32, 32, BATCH), dim3(32, 32)>>>(maskO, maskT);

    // 4) V->T attention
    enc3d(&tA, Qv, DT, SEQ, BATCH);
    enc3d(&tB, Kt, DT, SEQ, BATCH);
    gemm_tc<<<gb, NTHR, SMEM_DYN>>>(tA, tB, Ssc, S1);
    msoftmax_kernel<<<dim3(SEQ, BATCH), 256>>>(Ssc, maskO);
    enc3d(&tA, Ssc, SEQ, SEQ, BATCH);
    enc3d(&tB, VtT, SEQ, DT, BATCH);
    gemm_tc<<<gb, NTHR, SMEM_DYN>>>(tA, tB, out_vt, S1);

    // 5) T->V attention
    enc3d(&tA, Qt, DT, SEQ, BATCH);
    enc3d(&tB, Kv, DT, SEQ, BATCH);
    gemm_tc<<<gb, NTHR, SMEM_DYN>>>(tA, tB, Ssc, S1);
    msoftmax_kernel<<<dim3(SEQ, BATCH), 256>>>(Ssc, maskT);
    enc3d(&tA, Ssc, SEQ, SEQ, BATCH);
    enc3d(&tB, VvT, SEQ, DT, BATCH);
    gemm_tc<<<gb, NTHR, SMEM_DYN>>>(tA, tB, out_tv, S1);
}

// round 11
// speedup vs baseline: 1.0523x; 1.0523x over previous
#include <cuda_runtime.h>
#include <cuda.h>
#include <cstdint>

// ===========================================================================
#define BATCH 16
#define SEQ   1024
#define DT    1024
#define HID   512
#define NEG_INF_F (-1.0e9f)
static __device__ __host__ constexpr float INV_SQRT = 0.03125f;

static constexpr long ELEM1 = 16LL * 1024 * 1024;
__device__ __align__(1024) float g_scr[ELEM1 * 10 + 6L * DT * DT + 400000];

// ===========================================================================
// PTX helpers
// ===========================================================================
__device__ __forceinline__ uint32_t smem_u32(const void* p) {
    uint32_t a;
    asm("{ .reg .u64 t; cvta.to.shared.u64 t, %1; cvt.u32.u64 %0, t; }" : "=r"(a) : "l"(p));
    return a;
}
__device__ __forceinline__ uint32_t lds_u(uint32_t a) {
    uint32_t v;
    asm volatile("ld.shared.b32 %0, [%1];" : "=r"(v) : "r"(a));
    return v;
}
__device__ __forceinline__ float rnd_tf32(float f) {
    uint32_t r;
    asm volatile("cvt.rna.tf32.f32 %0, %1;" : "=r"(r) : "f"(f));
    return __uint_as_float(r);
}

#define MBARRIER_INIT(mbar, count) \
    asm volatile("mbarrier.init.shared.b64 [%0], %1;" :: "r"((uint32_t)(mbar)), "r"((uint32_t)(count)) : "memory")
#define MBARRIER_EXPECT_TX(mbar, bytes) \
    asm volatile("mbarrier.arrive.expect_tx.shared.b64 _, [%0], %1;" \
        :: "r"((uint32_t)(mbar)), "r"((uint32_t)(bytes)) : "memory")
#define MBARRIER_ARRIVE(mbar) \
    asm volatile("mbarrier.arrive.release.cta.shared.b64 _, [%0];" :: "r"((uint32_t)(mbar)) : "memory")
#define MBARRIER_WAIT_PARITY(mbar, parity) do {                                  \
    uint32_t _m = (uint32_t)(mbar);  uint32_t _p = (uint32_t)(parity);           \
    asm volatile(                                                                 \
        "{\n\t.reg .pred P1;\n\t"                                                 \
        "WL_%=:\n\t"                                                              \
        "mbarrier.try_wait.parity.acquire.cta.shared::cta.b64 P1, [%0], %1, 0x989680;\n\t" \
        "@P1 bra.uni WD_%=;\n\t"                                                  \
        "bra.uni WL_%=;\n\t"                                                      \
        "WD_%=:\n\t}"                                                             \
        :: "r"(_m), "r"(_p) : "memory");                                          \
} while (0)
#define TMA_LOAD_3D(saddr, tmap, cx, cy, cz, mbar) \
    asm volatile( \
        "cp.async.bulk.tensor.3d.shared::cta.global.tile.mbarrier::complete_tx::bytes " \
        "[%0], [%1, {%2, %3, %4}], [%5];" \
        :: "r"((uint32_t)(saddr)), "l"(tmap), "r"((int)(cx)), "r"((int)(cy)), "r"((int)(cz)), \
           "r"((uint32_t)(mbar)) : "memory")

// ===========================================================================
// GEMM config (R9 proven): CTA 128x128, KT=32/stage, 3 stages, 128 thr, 4 warps
// ===========================================================================
static constexpr int BM = 128, BN = 128, KT = 32, STAGES = 3;
static constexpr int ABYT = BM * KT * 4;
static constexpr int BBYT = BN * KT * 4;
static constexpr int STB  = ABYT + BBYT;
static constexpr int SMEM_DYN = 1024 + STAGES * STB;   // 99328
static constexpr int NTHR = 128;

#define GEMM_MAINLOOP(tmA_, tmB_, zA_, zB_)                                         \
    if (tid == 0) {                                                                 \
        for (int s_ = 0; s_ < STAGES; s_++) {                                       \
            MBARRIER_INIT(FULLB(s_), 1);                                            \
            MBARRIER_INIT(EMPTYB(s_), 4);                                           \
        }                                                                           \
    }                                                                               \
    __syncthreads();                                                                \
    if (tid == 0) {                                                                 \
        for (int s_ = 0; s_ < STAGES; s_++) {                                       \
            MBARRIER_EXPECT_TX(FULLB(s_), STB);                                     \
            TMA_LOAD_3D(sb + s_ * STB,        &(tmA_), s_ * KT, m0, (zA_), FULLB(s_)); \
            TMA_LOAD_3D(sb + s_ * STB + ABYT, &(tmB_), s_ * KT, n0, (zB_), FULLB(s_)); \
        }                                                                           \
    }                                                                               \
    const uint32_t gx   = (uint32_t)gID << 4;                                       \
    const uint32_t rowA = (uint32_t)(wm * 64 + gID) * 128;                          \
    const uint32_t rowB = (uint32_t)(wn * 64 + gID) * 128;                          \
    int s = 0, ph = 0;                                                              \
    for (int kt = 0; kt < 32; kt++) {                                               \
        const uint32_t stg = sb + s * STB;                                          \
        MBARRIER_WAIT_PARITY(FULLB(s), ph);                                         \
        const uint32_t aBase = stg + rowA;                                          \
        const uint32_t bBase = stg + ABYT + rowB;                                   \
        _Pragma("unroll")                                                           \
        for (int kk = 0; kk < 4; kk++) {                                            \
            const uint32_t off0 = ((uint32_t)(kk * 32 + tig * 4)) ^ gx;             \
            const uint32_t off1 = off0 ^ 16u;                                       \
            uint32_t ua[4][4], ub[8][2];                                            \
            _Pragma("unroll")                                                       \
            for (int mi = 0; mi < 4; mi++) {                                        \
                ua[mi][0] = lds_u(aBase + mi * 2048 + off0);                        \
                ua[mi][1] = lds_u(aBase + mi * 2048 + 1024 + off0);                 \
                ua[mi][2] = lds_u(aBase + mi * 2048 + off1);                        \
                ua[mi][3] = lds_u(aBase + mi * 2048 + 1024 + off1);                 \
            }                                                                       \
            _Pragma("unroll")                                                       \
            for (int ni = 0; ni < 8; ni++) {                                        \
                ub[ni][0] = lds_u(bBase + ni * 1024 + off0);                        \
                ub[ni][1] = lds_u(bBase + ni * 1024 + off1);                        \
            }                                                                       \
            _Pragma("unroll")                                                       \
            for (int mi = 0; mi < 4; mi++)                                          \
                _Pragma("unroll")                                                   \
                for (int ni = 0; ni < 8; ni++)                                      \
                    asm volatile(                                                   \
                        "mma.sync.aligned.m16n8k8.row.col.f32.tf32.tf32.f32 "       \
                        "{%0,%1,%2,%3},{%4,%5,%6,%7},{%8,%9},{%0,%1,%2,%3};"        \
                        : "+f"(acc[mi][ni][0]), "+f"(acc[mi][ni][1]),               \
                          "+f"(acc[mi][ni][2]), "+f"(acc[mi][ni][3])                \
                        : "r"(ua[mi][0]), "r"(ua[mi][1]), "r"(ua[mi][2]), "r"(ua[mi][3]), \
                          "r"(ub[ni][0]), "r"(ub[ni][1]));                          \
        }                                                                           \
        __syncwarp();                                                               \
        if (lane == 0) MBARRIER_ARRIVE(EMPTYB(s));                                  \
        if (tid == 0 && kt + STAGES < 32) {                                         \
            MBARRIER_WAIT_PARITY(EMPTYB(s), ph);                                    \
            MBARRIER_EXPECT_TX(FULLB(s), STB);                                      \
            TMA_LOAD_3D(sb + s * STB,        &(tmA_), (kt + STAGES) * KT, m0, (zA_), FULLB(s)); \
            TMA_LOAD_3D(sb + s * STB + ABYT, &(tmB_), (kt + STAGES) * KT, n0, (zB_), FULLB(s)); \
        }                                                                           \
        if (++s == STAGES) { s = 0; ph ^= 1; }                                      \
    }                                                                               \
    __syncthreads();

// ===========================================================================
// Batched GEMM (no bias): C[z][M,N] = A[z] @ B[z]^T
// ===========================================================================
__global__ void __launch_bounds__(NTHR, 2)
gemm_tc(const __grid_constant__ CUtensorMap tmA,
        const __grid_constant__ CUtensorMap tmB,
        float* __restrict__ C, long sCz)
{
    extern __shared__ char dynraw[];
    __shared__ __align__(8) unsigned long long mb[2 * STAGES];
    uint32_t d0 = smem_u32(dynraw);
    uint32_t sb = (d0 + 1023u) & ~1023u;
    const int tid = threadIdx.x;
    const int warp = tid >> 5, lane = tid & 31;
    const int wm = warp & 1, wn = warp >> 1;
    const int gID = lane >> 2, tig = lane & 3;
    const int m0 = blockIdx.y * BM, n0 = blockIdx.x * BN, z = blockIdx.z;
    const uint32_t mbase = smem_u32(mb);
#define FULLB(s)  (mbase + 8 * (s))
#define EMPTYB(s) (mbase + 24 + 8 * (s))

    float acc[4][8][4];
#pragma unroll
    for (int mi = 0; mi < 4; mi++)
#pragma unroll
        for (int ni = 0; ni < 8; ni++)
#pragma unroll
            for (int e = 0; e < 4; e++) acc[mi][ni][e] = 0.0f;

    GEMM_MAINLOOP(tmA, tmB, z, z)

    float* ep = (float*)(dynraw + (sb - d0));
    const int P = 132;
#pragma unroll
    for (int mi = 0; mi < 4; mi++)
#pragma unroll
        for (int ni = 0; ni < 8; ni++) {
            const int r = wm * 64 + mi * 16 + gID;
            const int c = wn * 64 + ni * 8 + 2 * tig;
            *(float2*)(ep + r * P + c)       = make_float2(acc[mi][ni][0], acc[mi][ni][1]);
            *(float2*)(ep + (r + 8) * P + c) = make_float2(acc[mi][ni][2], acc[mi][ni][3]);
        }
    __syncthreads();
    float* Cz = C + (long)z * sCz;
#pragma unroll
    for (int it = 0; it < 32; it++) {
        const int idx = tid + it * NTHR;
        const int r = idx >> 5, c4 = (idx & 31) * 4;
        float4 v = *(float4*)(ep + r * P + c4);
        *(float4*)(Cz + (long)(m0 + r) * 1024 + n0 + c4) = v;
    }
#undef FULLB
#undef EMPTYB
}

// ===========================================================================
// Wide projection GEMM: C[M, 3072] = A[M,1024] @ W[3072,1024]^T + biasC
// ===========================================================================
__global__ void __launch_bounds__(NTHR, 2)
gemm_proj(const __grid_constant__ CUtensorMap tmA,
          const __grid_constant__ CUtensorMap tmB,
          float* __restrict__ p0, float* __restrict__ p1, float* __restrict__ p2,
          const float* __restrict__ biasC, uint32_t trans_mask)
{
    extern __shared__ char dynraw[];
    __shared__ __align__(8) unsigned long long mb[2 * STAGES];
    uint32_t d0 = smem_u32(dynraw);
    uint32_t sb = (d0 + 1023u) & ~1023u;
    const int tid = threadIdx.x;
    const int warp = tid >> 5, lane = tid & 31;
    const int wm = warp & 1, wn = warp >> 1;
    const int gID = lane >> 2, tig = lane & 3;
    const int m0 = blockIdx.y * BM, n0 = blockIdx.x * BN;
    const uint32_t mbase = smem_u32(mb);
#define FULLB(s)  (mbase + 8 * (s))
#define EMPTYB(s) (mbase + 24 + 8 * (s))

    float acc[4][8][4];
#pragma unroll
    for (int mi = 0; mi < 4; mi++)
#pragma unroll
        for (int ni = 0; ni < 8; ni++)
#pragma unroll
            for (int e = 0; e < 4; e++) acc[mi][ni][e] = 0.0f;

    GEMM_MAINLOOP(tmA, tmB, 0, 0)

    // bias + round
#pragma unroll
    for (int ni = 0; ni < 8; ni++) {
        const int nc = n0 + wn * 64 + ni * 8 + 2 * tig;
        const float b0 = __ldg(biasC + nc), b1 = __ldg(biasC + nc + 1);
#pragma unroll
        for (int mi = 0; mi < 4; mi++) {
            acc[mi][ni][0] = rnd_tf32(acc[mi][ni][0] + b0);
            acc[mi][ni][1] = rnd_tf32(acc[mi][ni][1] + b1);
            acc[mi][ni][2] = rnd_tf32(acc[mi][ni][2] + b0);
            acc[mi][ni][3] = rnd_tf32(acc[mi][ni][3] + b1);
        }
    }

    const int sec = n0 >> 10;
    const int n0l = n0 & 1023;
    float* dst = (sec == 0) ? p0 : (sec == 1) ? p1 : p2;
    const bool tr = (trans_mask >> sec) & 1u;
    float* ep = (float*)(dynraw + (sb - d0));

    if (!tr) {
        const int P = 132;
#pragma unroll
        for (int mi = 0; mi < 4; mi++)
#pragma unroll
            for (int ni = 0; ni < 8; ni++) {
                const int r = wm * 64 + mi * 16 + gID;
                const int c = wn * 64 + ni * 8 + 2 * tig;
                *(float2*)(ep + r * P + c)       = make_float2(acc[mi][ni][0], acc[mi][ni][1]);
                *(float2*)(ep + (r + 8) * P + c) = make_float2(acc[mi][ni][2], acc[mi][ni][3]);
            }
        __syncthreads();
#pragma unroll
        for (int it = 0; it < 32; it++) {
            const int idx = tid + it * NTHR;
            const int r = idx >> 5, c4 = (idx & 31) * 4;
            float4 v = *(float4*)(ep + r * P + c4);
            *(float4*)(dst + (long)(m0 + r) * 1024 + n0l + c4) = v;
        }
    } else {
        const int P = 129;
#pragma unroll
        for (int mi = 0; mi < 4; mi++)
#pragma unroll
            for (int ni = 0; ni < 8; ni++) {
                const int r = wm * 64 + mi * 16 + gID;
                const int c = wn * 64 + ni * 8 + 2 * tig;
                ep[r * P + c]           = acc[mi][ni][0];
                ep[r * P + c + 1]       = acc[mi][ni][1];
                ep[(r + 8) * P + c]     = acc[mi][ni][2];
                ep[(r + 8) * P + c + 1] = acc[mi][ni][3];
            }
        __syncthreads();
        const int b   = m0 >> 10;
        const int mlb = m0 & 1023;
#pragma unroll 8
        for (int it = 0; it < 128; it++) {
            const int idx = tid + it * NTHR;
            const int n = idx >> 7, m = idx & 127;
            dst[((long)b << 20) + (long)(n0l + n) * 1024 + (mlb + m)] = ep[m * P + n];
        }
    }
#undef FULLB
#undef EMPTYB
}

// ===========================================================================
// Pre-round to tf32
// ===========================================================================
__global__ void round_kernel(const float4* __restrict__ in, float4* __restrict__ out, long n4)
{
    long i = (long)blockIdx.x * blockDim.x + threadIdx.x;
    long stride = (long)gridDim.x * blockDim.x;
    for (; i < n4; i += stride) {
        float4 v = in[i];
        v.x = rnd_tf32(v.x); v.y = rnd_tf32(v.y);
        v.z = rnd_tf32(v.z); v.w = rnd_tf32(v.w);
        out[i] = v;
    }
}

struct Ptr6 { const float4* in[6]; };
__global__ void round6_kernel(Ptr6 p, float4* __restrict__ out, long n4each)
{
    const float4* in = p.in[blockIdx.y];
    float4* o = out + blockIdx.y * n4each;
    long i = (long)blockIdx.x * blockDim.x + threadIdx.x;
    long stride = (long)gridDim.x * blockDim.x;
    for (; i < n4each; i += stride) {
        float4 v = in[i];
        v.x = rnd_tf32(v.x); v.y = rnd_tf32(v.y);
        v.z = rnd_tf32(v.z); v.w = rnd_tf32(v.w);
        o[i] = v;
    }
}

__global__ void cat_bias(const float* __restrict__ a, const float* __restrict__ b,
                         const float* __restrict__ c, float* __restrict__ o)
{
    int i = blockIdx.x * 256 + threadIdx.x;
    o[i] = (i < 1024) ? a[i] : (i < 2048) ? b[i - 1024] : c[i - 2048];
}

// ===========================================================================
// Two-stage mean pool
// ===========================================================================
__global__ void pool1_kernel(const float* __restrict__ src, float* __restrict__ part)
{
    int b = blockIdx.y, sp = blockIdx.z;
    int d = blockIdx.x * 256 + threadIdx.x;
    const float* p = src + ((long)b << 20) + ((long)sp << 17) + d;
    float s = 0.f;
#pragma unroll 16
    for (int m = 0; m < 128; m++) s += p[m << 10];
    part[(((b << 3) + sp) << 10) + d] = s;
}
__global__ void pool2_kernel(const float* __restrict__ part, float* __restrict__ dst)
{
    int b = blockIdx.y;
    int d = blockIdx.x * 256 + threadIdx.x;
    float s = 0.f;
#pragma unroll
    for (int sp = 0; sp < 8; sp++) s += part[(((b << 3) + sp) << 10) + d];
    dst[(b << 10) + d] = s * (1.0f / 1024.0f);
}

// ===========================================================================
// Gate FFN
// ===========================================================================
__global__ void ffn_kernel(const float* __restrict__ poolV, const float* __restrict__ poolT,
                           const float* __restrict__ w1, const float* __restrict__ b1,
                           const float* __restrict__ w2, const float* __restrict__ b2,
                           float* __restrict__ lout)
{
    __shared__ float x[2 * DT];
    __shared__ float red[HID];
    int b = blockIdx.x, t = threadIdx.x;
    for (int i = t; i < 2 * DT; i += HID)
        x[i] = (i < DT) ? poolV[b * DT + i] : poolT[b * DT + (i - DT)];
    __syncthreads();
    float acc = b1[t];
    const float* wr = w1 + (long)t * (2 * DT);
#pragma unroll 8
    for (int k = 0; k < 2 * DT; k++) acc += wr[k] * x[k];
    float h = fmaxf(acc, 0.0f);
    red[t] = h * w2[t];
    __syncthreads();
    for (int s = HID / 2; s > 0; s >>= 1) {
        if (t < s) red[t] += red[t + s];
        __syncthreads();
    }
    if (t == 0) lout[b] = 1.0f / (1.0f + expf(-(red[0] + b2[0])));
}

// ===========================================================================
// Warp reductions
// ===========================================================================
__device__ __forceinline__ float warp_max(float v)
{
#pragma unroll
    for (int o = 16; o > 0; o >>= 1)
        v = fmaxf(v, __shfl_xor_sync(0xFFFFFFFFu, v, o));
    return v;
}
__device__ __forceinline__ float warp_sum(float v)
{
#pragma unroll
    for (int o = 16; o > 0; o >>= 1)
        v += __shfl_xor_sync(0xFFFFFFFFu, v, o);
    return v;
}

// ===========================================================================
// Fused mask + transpose: softmax(sim*inv) >= l -> maskO (coalesced) AND
// maskT (SMEM-staged transpose). grid (BATCH, 32), block 256 (8 warps).
// Each block: 32-row m-strip; warp-per-row softmax via shfl (4 passes).
// ===========================================================================
__global__ void mask_trans_kernel(const float* __restrict__ S, const float* __restrict__ lv,
                                  float* __restrict__ maskO, float* __restrict__ maskT)
{
    __shared__ unsigned char tile[32][1028];   // pitch 1028 -> conflict-free
    const int b = blockIdx.x;
    const int m0g = blockIdx.y * 32;
    const int wid = threadIdx.x >> 5, lane = threadIdx.x & 31;
    const float l = lv[b];
    const long base = (long)b << 20;

    for (int rp = 0; rp < 4; rp++) {
        const int rl = rp * 8 + wid;          // local row 0..31
        const float4* p4 = (const float4*)(S + base + (long)(m0g + rl) * 1024);
        float4 x[8];
        float mx = -3.4e38f;
#pragma unroll
        for (int i = 0; i < 8; i++) {
            float4 v = p4[lane + i * 32];
            v.x *= INV_SQRT; v.y *= INV_SQRT; v.z *= INV_SQRT; v.w *= INV_SQRT;
            x[i] = v;
            mx = fmaxf(mx, fmaxf(fmaxf(v.x, v.y), fmaxf(v.z, v.w)));
        }
        mx = warp_max(mx);
        float ssum = 0.f;
        float4 e[8];
#pragma unroll
        for (int i = 0; i < 8; i++) {
            e[i].x = expf(x[i].x - mx); e[i].y = expf(x[i].y - mx);
            e[i].z = expf(x[i].z - mx); e[i].w = expf(x[i].w - mx);
            ssum += e[i].x + e[i].y + e[i].z + e[i].w;
        }
        ssum = warp_sum(ssum);
        const float thr = l * ssum;           // e/s >= l  <=>  e >= l*s  (s>0, l>=0)
        float4* o4 = (float4*)(maskO + base + (long)(m0g + rl) * 1024);
#pragma unroll
        for (int i = 0; i < 8; i++) {
            float4 mv;
            mv.x = (e[i].x >= thr) ? 1.0f : 0.0f;
            mv.y = (e[i].y >= thr) ? 1.0f : 0.0f;
            mv.z = (e[i].z >= thr) ? 1.0f : 0.0f;
            mv.w = (e[i].w >= thr) ? 1.0f : 0.0f;
            o4[lane + i * 32] = mv;
            uchar4 mb4 = make_uchar4((unsigned char)mv.x, (unsigned char)mv.y,
                                     (unsigned char)mv.z, (unsigned char)mv.w);
            *(uchar4*)&tile[rl][4 * (lane + i * 32)] = mb4;
        }
    }
    __syncthreads();
    // write maskT[b][n][m0g..m0g+31] from tile[m][n]
    for (int it = 0; it < 32; it++) {
        const int idx = threadIdx.x + it * 256;   // 0..8191
        const int n = idx >> 3, mq = (idx & 7) * 4;
        float4 v;
        v.x = (float)tile[mq + 0][n];
        v.y = (float)tile[mq + 1][n];
        v.z = (float)tile[mq + 2][n];
        v.w = (float)tile[mq + 3][n];
        *(float4*)(maskT + base + (long)n * 1024 + m0g + mq) = v;
    }
}

// ===========================================================================
// Masked softmax, warp-per-row, in place; outputs rounded to tf32.
// grid (128, BATCH), block 256 (8 warps).
// ===========================================================================
__global__ void msoftmax_kernel(float* __restrict__ S, const float* __restrict__ maskM)
{
    const int b = blockIdx.y;
    const int row = blockIdx.x * 8 + (threadIdx.x >> 5);
    const int lane = threadIdx.x & 31;
    const long base = ((long)b << 20) + (long)row * 1024;
    float4* p4 = (float4*)(S + base);
    const float4* mk4 = (const float4*)(maskM + base);

    float4 x[8];
    float mx = -3.4e38f;
#pragma unroll
    for (int i = 0; i < 8; i++) {
        float4 v = p4[lane + i * 32];
        float4 m = mk4[lane + i * 32];
        v.x = (m.x != 0.0f) ? v.x * INV_SQRT : NEG_INF_F;
        v.y = (m.y != 0.0f) ? v.y * INV_SQRT : NEG_INF_F;
        v.z = (m.z != 0.0f) ? v.z * INV_SQRT : NEG_INF_F;
        v.w = (m.w != 0.0f) ? v.w * INV_SQRT : NEG_INF_F;
        x[i] = v;
        mx = fmaxf(mx, fmaxf(fmaxf(v.x, v.y), fmaxf(v.z, v.w)));
    }
    mx = warp_max(mx);
    float ssum = 0.f;
#pragma unroll
    for (int i = 0; i < 8; i++) {
        x[i].x = expf(x[i].x - mx); x[i].y = expf(x[i].y - mx);
        x[i].z = expf(x[i].z - mx); x[i].w = expf(x[i].w - mx);
        ssum += x[i].x + x[i].y + x[i].z + x[i].w;
    }
    ssum = warp_sum(ssum);
    const float inv = 1.0f / ssum;
#pragma unroll
    for (int i = 0; i < 8; i++) {
        float4 v;
        v.x = rnd_tf32(x[i].x * inv); v.y = rnd_tf32(x[i].y * inv);
        v.z = rnd_tf32(x[i].z * inv); v.w = rnd_tf32(x[i].w * inv);
        p4[lane + i * 32] = v;
    }
}

// ===========================================================================
// Host side
// ===========================================================================
typedef CUresult (*PFN_encodeTiled)(CUtensorMap*, CUtensorMapDataType, cuuint32_t, void*,
                                    const cuuint64_t*, const cuuint64_t*, const cuuint32_t*,
                                    const cuuint32_t*, CUtensorMapInterleave, CUtensorMapSwizzle,
                                    CUtensorMapL2promotion, CUtensorMapFloatOOBfill);
static PFN_encodeTiled g_enc = nullptr;

static void enc3d(CUtensorMap* tm, const void* p, long K, long R, long Z)
{
    cuuint64_t dims[3] = {(cuuint64_t)K, (cuuint64_t)R, (cuuint64_t)Z};
    cuuint64_t str[2]  = {(cuuint64_t)(K * 4), (cuuint64_t)(K * R * 4)};
    cuuint32_t box[3]  = {(cuuint32_t)KT, 128, 1};
    cuuint32_t es[3]   = {1, 1, 1};
    g_enc(tm, CU_TENSOR_MAP_DATA_TYPE_FLOAT32, 3, (void*)p, dims, str, box, es,
          CU_TENSOR_MAP_INTERLEAVE_NONE, CU_TENSOR_MAP_SWIZZLE_128B,
          CU_TENSOR_MAP_L2_PROMOTION_L2_128B, CU_TENSOR_MAP_FLOAT_OOB_FILL_NONE);
}

extern "C" void kernel_launch(void* const* d_in, const int* in_sizes, int n_in,
                              void* d_out, int out_size)
{
    (void)in_sizes; (void)n_in; (void)out_size;

    const float* oV     = (const float*)d_in[0];
    const float* oT     = (const float*)d_in[1];
    const float* Wq_v_w = (const float*)d_in[2];
    const float* Wq_v_b = (const float*)d_in[3];
    const float* Wk_t_w = (const float*)d_in[4];
    const float* Wk_t_b = (const float*)d_in[5];
    const float* Wv_t_w = (const float*)d_in[6];
    const float* Wv_t_b = (const float*)d_in[7];
    const float* Wq_t_w = (const float*)d_in[8];
    const float* Wq_t_b = (const float*)d_in[9];
    const float* Wk_v_w = (const float*)d_in[10];
    const float* Wk_v_b = (const float*)d_in[11];
    const float* Wv_v_w = (const float*)d_in[12];
    const float* Wv_v_b = (const float*)d_in[13];
    const float* ffn1_w = (const float*)d_in[14];
    const float* ffn1_b = (const float*)d_in[15];
    const float* ffn2_w = (const float*)d_in[16];
    const float* ffn2_b = (const float*)d_in[17];

    float* out_vt = (float*)d_out;
    float* out_tv = out_vt + ELEM1;
    float* maskO  = out_vt + 2 * ELEM1;

    static float* scr = nullptr;
    if (!scr) cudaGetSymbolAddress((void**)&scr, g_scr);
    if (!g_enc) {
        void* p = nullptr;
        cudaDriverEntryPointQueryResult st;
        cudaGetDriverEntryPoint("cuTensorMapEncodeTiled", &p, cudaEnableDefault, &st);
        g_enc = (PFN_encodeTiled)p;
    }
    static bool attr_done = false;
    if (!attr_done) {
        cudaFuncSetAttribute(gemm_tc,   cudaFuncAttributeMaxDynamicSharedMemorySize, SMEM_DYN);
        cudaFuncSetAttribute(gemm_proj, cudaFuncAttributeMaxDynamicSharedMemorySize, SMEM_DYN);
        attr_done = true;
    }

    float* Qv    = scr + 0 * ELEM1;
    float* Kt    = scr + 1 * ELEM1;
    float* VtT   = scr + 2 * ELEM1;   // (B, DT, SEQ)
    float* Qt    = scr + 3 * ELEM1;
    float* Kv    = scr + 4 * ELEM1;
    float* VvT   = scr + 5 * ELEM1;   // (B, DT, SEQ)
    float* Ssc   = scr + 6 * ELEM1;
    float* maskT = scr + 7 * ELEM1;
    float* oVr   = scr + 8 * ELEM1;
    float* oTr   = scr + 9 * ELEM1;
    float* Wr    = scr + 10 * ELEM1;
    float* poolV = Wr + 6L * DT * DT;
    float* poolT = poolV + BATCH * DT;
    float* lv    = poolT + BATCH * DT;
    float* partV = lv + 64;
    float* partT = partV + 8 * BATCH * 1024;
    float* biasV = partT + 8 * BATCH * 1024;
    float* biasT = biasV + 3072;

    // 0) pre-round GEMM inputs
    const long N4BIG = ELEM1 / 4;
    round_kernel<<<2048, 256>>>((const float4*)oV, (float4*)oVr, N4BIG);
    round_kernel<<<2048, 256>>>((const float4*)oT, (float4*)oTr, N4BIG);
    Ptr6 wp;
    wp.in[0] = (const float4*)Wq_v_w;  wp.in[1] = (const float4*)Wk_v_w;
    wp.in[2] = (const float4*)Wv_v_w;  wp.in[3] = (const float4*)Wk_t_w;
    wp.in[4] = (const float4*)Wv_t_w;  wp.in[5] = (const float4*)Wq_t_w;
    round6_kernel<<<dim3(256, 6), 256>>>(wp, (float4*)Wr, (long)DT * DT / 4);
    cat_bias<<<12, 256>>>(Wq_v_b, Wk_v_b, Wv_v_b, biasV);
    cat_bias<<<12, 256>>>(Wk_t_b, Wv_t_b, Wq_t_b, biasT);

    // 1) pools + gate
    pool1_kernel<<<dim3(4, BATCH, 8), 256>>>(oV, partV);
    pool1_kernel<<<dim3(4, BATCH, 8), 256>>>(oT, partT);
    pool2_kernel<<<dim3(4, BATCH), 256>>>(partV, poolV);
    pool2_kernel<<<dim3(4, BATCH), 256>>>(partT, poolT);
    ffn_kernel<<<BATCH, HID>>>(poolV, poolT, ffn1_w, ffn1_b, ffn2_w, ffn2_b, lv);

    CUtensorMap tA, tB;
    const dim3 gw(24, 128, 1);
    const dim3 gb(8, 8, BATCH);

    // 2) projections: 2 wide GEMMs
    enc3d(&tA, oVr, DT, BATCH * SEQ, 1);
    enc3d(&tB, Wr, DT, 3 * DT, 1);
    gemm_proj<<<gw, NTHR, SMEM_DYN>>>(tA, tB, Qv, Kv, VvT, biasV, 0b100u);

    enc3d(&tA, oTr, DT, BATCH * SEQ, 1);
    enc3d(&tB, Wr + 3L * DT * DT, DT, 3 * DT, 1);
    gemm_proj<<<gw, NTHR, SMEM_DYN>>>(tA, tB, Kt, VtT, Qt, biasT, 0b010u);

    const long S1 = (long)SEQ * SEQ;

    // 3) sim -> fused mask + maskT
    enc3d(&tA, oVr, DT, SEQ, BATCH);
    enc3d(&tB, oTr, DT, SEQ, BATCH);
    gemm_tc<<<gb, NTHR, SMEM_DYN>>>(tA, tB, Ssc, S1);
    mask_trans_kernel<<<dim3(BATCH, 32), 256>>>(Ssc, lv, maskO, maskT);

    // 4) V->T attention
    enc3d(&tA, Qv, DT, SEQ, BATCH);
    enc3d(&tB, Kt, DT, SEQ, BATCH);
    gemm_tc<<<gb, NTHR, SMEM_DYN>>>(tA, tB, Ssc, S1);
    msoftmax_kernel<<<dim3(128, BATCH), 256>>>(Ssc, maskO);
    enc3d(&tA, Ssc, SEQ, SEQ, BATCH);
    enc3d(&tB, VtT, SEQ, DT, BATCH);
    gemm_tc<<<gb, NTHR, SMEM_DYN>>>(tA, tB, out_vt, S1);

    // 5) T->V attention
    enc3d(&tA, Qt, DT, SEQ, BATCH);
    enc3d(&tB, Kv, DT, SEQ, BATCH);
    gemm_tc<<<gb, NTHR, SMEM_DYN>>>(tA, tB, Ssc, S1);
    msoftmax_kernel<<<dim3(128, BATCH), 256>>>(Ssc, maskT);
    enc3d(&tA, Ssc, SEQ, SEQ, BATCH);
    enc3d(&tB, VvT, SEQ, DT, BATCH);
    gemm_tc<<<gb, NTHR, SMEM_DYN>>>(tA, tB, out_tv, S1);
}

// round 13
// speedup vs baseline: 1.0885x; 1.0344x over previous
#include <cuda_runtime.h>
#include <cuda.h>
#include <cstdint>

// ===========================================================================
#define BATCH 16
#define SEQ   1024
#define DT    1024
#define HID   512
#define NEG_INF_F (-1.0e9f)
static __device__ __host__ constexpr float INV_SQRT = 0.03125f;

static constexpr long ELEM1 = 16LL * 1024 * 1024;
__device__ __align__(1024) float g_scr[ELEM1 * 11 + 6L * DT * DT + 400000];

// ===========================================================================
// PTX helpers
// ===========================================================================
__device__ __forceinline__ uint32_t smem_u32(const void* p) {
    uint32_t a;
    asm("{ .reg .u64 t; cvta.to.shared.u64 t, %1; cvt.u32.u64 %0, t; }" : "=r"(a) : "l"(p));
    return a;
}
__device__ __forceinline__ uint32_t lds_u(uint32_t a) {
    uint32_t v;
    asm volatile("ld.shared.b32 %0, [%1];" : "=r"(v) : "r"(a));
    return v;
}
__device__ __forceinline__ float rnd_tf32(float f) {
    uint32_t r;
    asm volatile("cvt.rna.tf32.f32 %0, %1;" : "=r"(r) : "f"(f));
    return __uint_as_float(r);
}

#define MBARRIER_INIT(mbar, count) \
    asm volatile("mbarrier.init.shared.b64 [%0], %1;" :: "r"((uint32_t)(mbar)), "r"((uint32_t)(count)) : "memory")
#define MBARRIER_EXPECT_TX(mbar, bytes) \
    asm volatile("mbarrier.arrive.expect_tx.shared.b64 _, [%0], %1;" \
        :: "r"((uint32_t)(mbar)), "r"((uint32_t)(bytes)) : "memory")
#define MBARRIER_ARRIVE(mbar) \
    asm volatile("mbarrier.arrive.release.cta.shared.b64 _, [%0];" :: "r"((uint32_t)(mbar)) : "memory")
#define MBARRIER_WAIT_PARITY(mbar, parity) do {                                  \
    uint32_t _m = (uint32_t)(mbar);  uint32_t _p = (uint32_t)(parity);           \
    asm volatile(                                                                 \
        "{\n\t.reg .pred P1;\n\t"                                                 \
        "WL_%=:\n\t"                                                              \
        "mbarrier.try_wait.parity.acquire.cta.shared::cta.b64 P1, [%0], %1, 0x989680;\n\t" \
        "@P1 bra.uni WD_%=;\n\t"                                                  \
        "bra.uni WL_%=;\n\t"                                                      \
        "WD_%=:\n\t}"                                                             \
        :: "r"(_m), "r"(_p) : "memory");                                          \
} while (0)
#define TMA_LOAD_3D(saddr, tmap, cx, cy, cz, mbar) \
    asm volatile( \
        "cp.async.bulk.tensor.3d.shared::cta.global.tile.mbarrier::complete_tx::bytes " \
        "[%0], [%1, {%2, %3, %4}], [%5];" \
        :: "r"((uint32_t)(saddr)), "l"(tmap), "r"((int)(cx)), "r"((int)(cy)), "r"((int)(cz)), \
           "r"((uint32_t)(mbar)) : "memory")

// ===========================================================================
// GEMM config: CTA 128x128, KT=32/stage, 3 stages, 128 thr, 4 warps (64x64)
// ===========================================================================
static constexpr int BM = 128, BN = 128, KT = 32, STAGES = 3;
static constexpr int ABYT = BM * KT * 4;
static constexpr int BBYT = BN * KT * 4;
static constexpr int STB  = ABYT + BBYT;
static constexpr int SMEM_DYN = 1024 + STAGES * STB;   // 99328
static constexpr int NTHR = 128;

#define GEMM_MAINLOOP(tmA_, tmB_, zA_, zB_)                                         \
    if (tid == 0) {                                                                 \
        for (int s_ = 0; s_ < STAGES; s_++) {                                       \
            MBARRIER_INIT(FULLB(s_), 1);                                            \
            MBARRIER_INIT(EMPTYB(s_), 4);                                           \
        }                                                                           \
    }                                                                               \
    __syncthreads();                                                                \
    if (tid == 0) {                                                                 \
        for (int s_ = 0; s_ < STAGES; s_++) {                                       \
            MBARRIER_EXPECT_TX(FULLB(s_), STB);                                     \
            TMA_LOAD_3D(sb + s_ * STB,        &(tmA_), s_ * KT, m0, (zA_), FULLB(s_)); \
            TMA_LOAD_3D(sb + s_ * STB + ABYT, &(tmB_), s_ * KT, n0, (zB_), FULLB(s_)); \
        }                                                                           \
    }                                                                               \
    const uint32_t gx   = (uint32_t)gID << 4;                                       \
    const uint32_t rowA = (uint32_t)(wm * 64 + gID) * 128;                          \
    const uint32_t rowB = (uint32_t)(wn * 64 + gID) * 128;                          \
    int s = 0, ph = 0;                                                              \
    for (int kt = 0; kt < 32; kt++) {                                               \
        const uint32_t stg = sb + s * STB;                                          \
        MBARRIER_WAIT_PARITY(FULLB(s), ph);                                         \
        const uint32_t aBase = stg + rowA;                                          \
        const uint32_t bBase = stg + ABYT + rowB;                                   \
        _Pragma("unroll")                                                           \
        for (int kk = 0; kk < 4; kk++) {                                            \
            const uint32_t off0 = ((uint32_t)(kk * 32 + tig * 4)) ^ gx;             \
            const uint32_t off1 = off0 ^ 16u;                                       \
            uint32_t ua[4][4], ub[8][2];                                            \
            _Pragma("unroll")                                                       \
            for (int mi = 0; mi < 4; mi++) {                                        \
                ua[mi][0] = lds_u(aBase + mi * 2048 + off0);                        \
                ua[mi][1] = lds_u(aBase + mi * 2048 + 1024 + off0);                 \
                ua[mi][2] = lds_u(aBase + mi * 2048 + off1);                        \
                ua[mi][3] = lds_u(aBase + mi * 2048 + 1024 + off1);                 \
            }                                                                       \
            _Pragma("unroll")                                                       \
            for (int ni = 0; ni < 8; ni++) {                                        \
                ub[ni][0] = lds_u(bBase + ni * 1024 + off0);                        \
                ub[ni][1] = lds_u(bBase + ni * 1024 + off1);                        \
            }                                                                       \
            _Pragma("unroll")                                                       \
            for (int mi = 0; mi < 4; mi++)                                          \
                _Pragma("unroll")                                                   \
                for (int ni = 0; ni < 8; ni++)                                      \
                    asm volatile(                                                   \
                        "mma.sync.aligned.m16n8k8.row.col.f32.tf32.tf32.f32 "       \
                        "{%0,%1,%2,%3},{%4,%5,%6,%7},{%8,%9},{%0,%1,%2,%3};"        \
                        : "+f"(acc[mi][ni][0]), "+f"(acc[mi][ni][1]),               \
                          "+f"(acc[mi][ni][2]), "+f"(acc[mi][ni][3])                \
                        : "r"(ua[mi][0]), "r"(ua[mi][1]), "r"(ua[mi][2]), "r"(ua[mi][3]), \
                          "r"(ub[ni][0]), "r"(ub[ni][1]));                          \
        }                                                                           \
        __syncwarp();                                                               \
        if (lane == 0) MBARRIER_ARRIVE(EMPTYB(s));                                  \
        if (tid == 0 && kt + STAGES < 32) {                                         \
            MBARRIER_WAIT_PARITY(EMPTYB(s), ph);                                    \
            MBARRIER_EXPECT_TX(FULLB(s), STB);                                      \
            TMA_LOAD_3D(sb + s * STB,        &(tmA_), (kt + STAGES) * KT, m0, (zA_), FULLB(s)); \
            TMA_LOAD_3D(sb + s * STB + ABYT, &(tmB_), (kt + STAGES) * KT, n0, (zB_), FULLB(s)); \
        }                                                                           \
        if (++s == STAGES) { s = 0; ph ^= 1; }                                      \
    }                                                                               \
    __syncthreads();

// ===========================================================================
// Batched GEMM (no bias): C[z][M,N] = A[z] @ B[z]^T
// ===========================================================================
__global__ void __launch_bounds__(NTHR, 2)
gemm_tc(const __grid_constant__ CUtensorMap tmA,
        const __grid_constant__ CUtensorMap tmB,
        float* __restrict__ C, long sCz)
{
    extern __shared__ char dynraw[];
    __shared__ __align__(8) unsigned long long mb[2 * STAGES];
    uint32_t d0 = smem_u32(dynraw);
    uint32_t sb = (d0 + 1023u) & ~1023u;
    const int tid = threadIdx.x;
    const int warp = tid >> 5, lane = tid & 31;
    const int wm = warp & 1, wn = warp >> 1;
    const int gID = lane >> 2, tig = lane & 3;
    const int m0 = blockIdx.y * BM, n0 = blockIdx.x * BN, z = blockIdx.z;
    const uint32_t mbase = smem_u32(mb);
#define FULLB(s)  (mbase + 8 * (s))
#define EMPTYB(s) (mbase + 24 + 8 * (s))

    float acc[4][8][4];
#pragma unroll
    for (int mi = 0; mi < 4; mi++)
#pragma unroll
        for (int ni = 0; ni < 8; ni++)
#pragma unroll
            for (int e = 0; e < 4; e++) acc[mi][ni][e] = 0.0f;

    GEMM_MAINLOOP(tmA, tmB, z, z)

    float* ep = (float*)(dynraw + (sb - d0));
    const int P = 132;
#pragma unroll
    for (int mi = 0; mi < 4; mi++)
#pragma unroll
        for (int ni = 0; ni < 8; ni++) {
            const int r = wm * 64 + mi * 16 + gID;
            const int c = wn * 64 + ni * 8 + 2 * tig;
            *(float2*)(ep + r * P + c)       = make_float2(acc[mi][ni][0], acc[mi][ni][1]);
            *(float2*)(ep + (r + 8) * P + c) = make_float2(acc[mi][ni][2], acc[mi][ni][3]);
        }
    __syncthreads();
    float* Cz = C + (long)z * sCz;
#pragma unroll
    for (int it = 0; it < 32; it++) {
        const int idx = tid + it * NTHR;
        const int r = idx >> 5, c4 = (idx & 31) * 4;
        float4 v = *(float4*)(ep + r * P + c4);
        *(float4*)(Cz + (long)(m0 + r) * 1024 + n0 + c4) = v;
    }
#undef FULLB
#undef EMPTYB
}

// ===========================================================================
// Wide projection GEMM: C[M, 3072] = A[M,1024] @ W[3072,1024]^T + biasC
// ===========================================================================
__global__ void __launch_bounds__(NTHR, 2)
gemm_proj(const __grid_constant__ CUtensorMap tmA,
          const __grid_constant__ CUtensorMap tmB,
          float* __restrict__ p0, float* __restrict__ p1, float* __restrict__ p2,
          const float* __restrict__ biasC, uint32_t trans_mask)
{
    extern __shared__ char dynraw[];
    __shared__ __align__(8) unsigned long long mb[2 * STAGES];
    uint32_t d0 = smem_u32(dynraw);
    uint32_t sb = (d0 + 1023u) & ~1023u;
    const int tid = threadIdx.x;
    const int warp = tid >> 5, lane = tid & 31;
    const int wm = warp & 1, wn = warp >> 1;
    const int gID = lane >> 2, tig = lane & 3;
    const int m0 = blockIdx.y * BM, n0 = blockIdx.x * BN;
    const uint32_t mbase = smem_u32(mb);
#define FULLB(s)  (mbase + 8 * (s))
#define EMPTYB(s) (mbase + 24 + 8 * (s))

    float acc[4][8][4];
#pragma unroll
    for (int mi = 0; mi < 4; mi++)
#pragma unroll
        for (int ni = 0; ni < 8; ni++)
#pragma unroll
            for (int e = 0; e < 4; e++) acc[mi][ni][e] = 0.0f;

    GEMM_MAINLOOP(tmA, tmB, 0, 0)

    // bias + round
#pragma unroll
    for (int ni = 0; ni < 8; ni++) {
        const int nc = n0 + wn * 64 + ni * 8 + 2 * tig;
        const float b0 = __ldg(biasC + nc), b1 = __ldg(biasC + nc + 1);
#pragma unroll
        for (int mi = 0; mi < 4; mi++) {
            acc[mi][ni][0] = rnd_tf32(acc[mi][ni][0] + b0);
            acc[mi][ni][1] = rnd_tf32(acc[mi][ni][1] + b1);
            acc[mi][ni][2] = rnd_tf32(acc[mi][ni][2] + b0);
            acc[mi][ni][3] = rnd_tf32(acc[mi][ni][3] + b1);
        }
    }

    const int sec = n0 >> 10;
    const int n0l = n0 & 1023;
    float* dst = (sec == 0) ? p0 : (sec == 1) ? p1 : p2;
    const bool tr = (trans_mask >> sec) & 1u;
    float* ep = (float*)(dynraw + (sb - d0));

    if (!tr) {
        const int P = 132;
#pragma unroll
        for (int mi = 0; mi < 4; mi++)
#pragma unroll
            for (int ni = 0; ni < 8; ni++) {
                const int r = wm * 64 + mi * 16 + gID;
                const int c = wn * 64 + ni * 8 + 2 * tig;
                *(float2*)(ep + r * P + c)       = make_float2(acc[mi][ni][0], acc[mi][ni][1]);
                *(float2*)(ep + (r + 8) * P + c) = make_float2(acc[mi][ni][2], acc[mi][ni][3]);
            }
        __syncthreads();
#pragma unroll
        for (int it = 0; it < 32; it++) {
            const int idx = tid + it * NTHR;
            const int r = idx >> 5, c4 = (idx & 31) * 4;
            float4 v = *(float4*)(ep + r * P + c4);
            *(float4*)(dst + (long)(m0 + r) * 1024 + n0l + c4) = v;
        }
    } else {
        const int P = 129;
#pragma unroll
        for (int mi = 0; mi < 4; mi++)
#pragma unroll
            for (int ni = 0; ni < 8; ni++) {
                const int r = wm * 64 + mi * 16 + gID;
                const int c = wn * 64 + ni * 8 + 2 * tig;
                ep[r * P + c]           = acc[mi][ni][0];
                ep[r * P + c + 1]       = acc[mi][ni][1];
                ep[(r + 8) * P + c]     = acc[mi][ni][2];
                ep[(r + 8) * P + c + 1] = acc[mi][ni][3];
            }
        __syncthreads();
        const int b   = m0 >> 10;
        const int mlb = m0 & 1023;
#pragma unroll 8
        for (int it = 0; it < 128; it++) {
            const int idx = tid + it * NTHR;
            const int n = idx >> 7, m = idx & 127;
            dst[((long)b << 20) + (long)(n0l + n) * 1024 + (mlb + m)] = ep[m * P + n];
        }
    }
#undef FULLB
#undef EMPTYB
}

// ===========================================================================
// Pre-round to tf32
// ===========================================================================
__global__ void round_kernel(const float4* __restrict__ in, float4* __restrict__ out, long n4)
{
    long i = (long)blockIdx.x * blockDim.x + threadIdx.x;
    long stride = (long)gridDim.x * blockDim.x;
    for (; i < n4; i += stride) {
        float4 v = in[i];
        v.x = rnd_tf32(v.x); v.y = rnd_tf32(v.y);
        v.z = rnd_tf32(v.z); v.w = rnd_tf32(v.w);
        out[i] = v;
    }
}

struct Ptr6 { const float4* in[6]; };
__global__ void round6_kernel(Ptr6 p, float4* __restrict__ out, long n4each)
{
    const float4* in = p.in[blockIdx.y];
    float4* o = out + blockIdx.y * n4each;
    long i = (long)blockIdx.x * blockDim.x + threadIdx.x;
    long stride = (long)gridDim.x * blockDim.x;
    for (; i < n4each; i += stride) {
        float4 v = in[i];
        v.x = rnd_tf32(v.x); v.y = rnd_tf32(v.y);
        v.z = rnd_tf32(v.z); v.w = rnd_tf32(v.w);
        o[i] = v;
    }
}

__global__ void cat_bias(const float* __restrict__ a, const float* __restrict__ b,
                         const float* __restrict__ c, float* __restrict__ o)
{
    int i = blockIdx.x * 256 + threadIdx.x;
    o[i] = (i < 1024) ? a[i] : (i < 2048) ? b[i - 1024] : c[i - 2048];
}

// ===========================================================================
// Two-stage mean pool
// ===========================================================================
__global__ void pool1_kernel(const float* __restrict__ src, float* __restrict__ part)
{
    int b = blockIdx.y, sp = blockIdx.z;
    int d = blockIdx.x * 256 + threadIdx.x;
    const float* p = src + ((long)b << 20) + ((long)sp << 17) + d;
    float s = 0.f;
#pragma unroll 16
    for (int m = 0; m < 128; m++) s += p[m << 10];
    part[(((b << 3) + sp) << 10) + d] = s;
}
__global__ void pool2_kernel(const float* __restrict__ part, float* __restrict__ dst)
{
    int b = blockIdx.y;
    int d = blockIdx.x * 256 + threadIdx.x;
    float s = 0.f;
#pragma unroll
    for (int sp = 0; sp < 8; sp++) s += part[(((b << 3) + sp) << 10) + d];
    dst[(b << 10) + d] = s * (1.0f / 1024.0f);
}

// ===========================================================================
// Gate FFN
// ===========================================================================
__global__ void ffn_kernel(const float* __restrict__ poolV, const float* __restrict__ poolT,
                           const float* __restrict__ w1, const float* __restrict__ b1,
                           const float* __restrict__ w2, const float* __restrict__ b2,
                           float* __restrict__ lout)
{
    __shared__ float x[2 * DT];
    __shared__ float red[HID];
    int b = blockIdx.x, t = threadIdx.x;
    for (int i = t; i < 2 * DT; i += HID)
        x[i] = (i < DT) ? poolV[b * DT + i] : poolT[b * DT + (i - DT)];
    __syncthreads();
    float acc = b1[t];
    const float* wr = w1 + (long)t * (2 * DT);
#pragma unroll 8
    for (int k = 0; k < 2 * DT; k++) acc += wr[k] * x[k];
    float h = fmaxf(acc, 0.0f);
    red[t] = h * w2[t];
    __syncthreads();
    for (int s = HID / 2; s > 0; s >>= 1) {
        if (t < s) red[t] += red[t + s];
        __syncthreads();
    }
    if (t == 0) lout[b] = 1.0f / (1.0f + expf(-(red[0] + b2[0])));
}

// ===========================================================================
// Warp reductions
// ===========================================================================
__device__ __forceinline__ float warp_max(float v)
{
#pragma unroll
    for (int o = 16; o > 0; o >>= 1)
        v = fmaxf(v, __shfl_xor_sync(0xFFFFFFFFu, v, o));
    return v;
}
__device__ __forceinline__ float warp_sum(float v)
{
#pragma unroll
    for (int o = 16; o > 0; o >>= 1)
        v += __shfl_xor_sync(0xFFFFFFFFu, v, o);
    return v;
}

// ===========================================================================
// Fused mask + transpose
// ===========================================================================
__global__ void mask_trans_kernel(const float* __restrict__ S, const float* __restrict__ lv,
                                  float* __restrict__ maskO, float* __restrict__ maskT)
{
    __shared__ unsigned char tile[32][1028];
    const int b = blockIdx.x;
    const int m0g = blockIdx.y * 32;
    const int wid = threadIdx.x >> 5, lane = threadIdx.x & 31;
    const float l = lv[b];
    const long base = (long)b << 20;

    for (int rp = 0; rp < 4; rp++) {
        const int rl = rp * 8 + wid;
        const float4* p4 = (const float4*)(S + base + (long)(m0g + rl) * 1024);
        float4 x[8];
        float mx = -3.4e38f;
#pragma unroll
        for (int i = 0; i < 8; i++) {
            float4 v = p4[lane + i * 32];
            v.x *= INV_SQRT; v.y *= INV_SQRT; v.z *= INV_SQRT; v.w *= INV_SQRT;
            x[i] = v;
            mx = fmaxf(mx, fmaxf(fmaxf(v.x, v.y), fmaxf(v.z, v.w)));
        }
        mx = warp_max(mx);
        float ssum = 0.f;
        float4 e[8];
#pragma unroll
        for (int i = 0; i < 8; i++) {
            e[i].x = expf(x[i].x - mx); e[i].y = expf(x[i].y - mx);
            e[i].z = expf(x[i].z - mx); e[i].w = expf(x[i].w - mx);
            ssum += e[i].x + e[i].y + e[i].z + e[i].w;
        }
        ssum = warp_sum(ssum);
        const float thr = l * ssum;
        float4* o4 = (float4*)(maskO + base + (long)(m0g + rl) * 1024);
#pragma unroll
        for (int i = 0; i < 8; i++) {
            float4 mv;
            mv.x = (e[i].x >= thr) ? 1.0f : 0.0f;
            mv.y = (e[i].y >= thr) ? 1.0f : 0.0f;
            mv.z = (e[i].z >= thr) ? 1.0f : 0.0f;
            mv.w = (e[i].w >= thr) ? 1.0f : 0.0f;
            o4[lane + i * 32] = mv;
            uchar4 mb4 = make_uchar4((unsigned char)mv.x, (unsigned char)mv.y,
                                     (unsigned char)mv.z, (unsigned char)mv.w);
            *(uchar4*)&tile[rl][4 * (lane + i * 32)] = mb4;
        }
    }
    __syncthreads();
    for (int it = 0; it < 32; it++) {
        const int idx = threadIdx.x + it * 256;
        const int n = idx >> 3, mq = (idx & 7) * 4;
        float4 v;
        v.x = (float)tile[mq + 0][n];
        v.y = (float)tile[mq + 1][n];
        v.z = (float)tile[mq + 2][n];
        v.w = (float)tile[mq + 3][n];
        *(float4*)(maskT + base + (long)n * 1024 + m0g + mq) = v;
    }
}

// ===========================================================================
// Masked softmax, warp-per-row, in place; outputs rounded to tf32.
// ===========================================================================
__global__ void msoftmax_kernel(float* __restrict__ S, const float* __restrict__ maskM)
{
    const int b = blockIdx.y;
    const int row = blockIdx.x * 8 + (threadIdx.x >> 5);
    const int lane = threadIdx.x & 31;
    const long base = ((long)b << 20) + (long)row * 1024;
    float4* p4 = (float4*)(S + base);
    const float4* mk4 = (const float4*)(maskM + base);

    float4 x[8];
    float mx = -3.4e38f;
#pragma unroll
    for (int i = 0; i < 8; i++) {
        float4 v = p4[lane + i * 32];
        float4 m = mk4[lane + i * 32];
        v.x = (m.x != 0.0f) ? v.x * INV_SQRT : NEG_INF_F;
        v.y = (m.y != 0.0f) ? v.y * INV_SQRT : NEG_INF_F;
        v.z = (m.z != 0.0f) ? v.z * INV_SQRT : NEG_INF_F;
        v.w = (m.w != 0.0f) ? v.w * INV_SQRT : NEG_INF_F;
        x[i] = v;
        mx = fmaxf(mx, fmaxf(fmaxf(v.x, v.y), fmaxf(v.z, v.w)));
    }
    mx = warp_max(mx);
    float ssum = 0.f;
#pragma unroll
    for (int i = 0; i < 8; i++) {
        x[i].x = expf(x[i].x - mx); x[i].y = expf(x[i].y - mx);
        x[i].z = expf(x[i].z - mx); x[i].w = expf(x[i].w - mx);
        ssum += x[i].x + x[i].y + x[i].z + x[i].w;
    }
    ssum = warp_sum(ssum);
    const float inv = 1.0f / ssum;
#pragma unroll
    for (int i = 0; i < 8; i++) {
        float4 v;
        v.x = rnd_tf32(x[i].x * inv); v.y = rnd_tf32(x[i].y * inv);
        v.z = rnd_tf32(x[i].z * inv); v.w = rnd_tf32(x[i].w * inv);
        p4[lane + i * 32] = v;
    }
}

// ===========================================================================
// Host side
// ===========================================================================
typedef CUresult (*PFN_encodeTiled)(CUtensorMap*, CUtensorMapDataType, cuuint32_t, void*,
                                    const cuuint64_t*, const cuuint64_t*, const cuuint32_t*,
                                    const cuuint32_t*, CUtensorMapInterleave, CUtensorMapSwizzle,
                                    CUtensorMapL2promotion, CUtensorMapFloatOOBfill);
static PFN_encodeTiled g_enc = nullptr;

static void enc3d(CUtensorMap* tm, const void* p, long K, long R, long Z)
{
    cuuint64_t dims[3] = {(cuuint64_t)K, (cuuint64_t)R, (cuuint64_t)Z};
    cuuint64_t str[2]  = {(cuuint64_t)(K * 4), (cuuint64_t)(K * R * 4)};
    cuuint32_t box[3]  = {(cuuint32_t)KT, 128, 1};
    cuuint32_t es[3]   = {1, 1, 1};
    g_enc(tm, CU_TENSOR_MAP_DATA_TYPE_FLOAT32, 3, (void*)p, dims, str, box, es,
          CU_TENSOR_MAP_INTERLEAVE_NONE, CU_TENSOR_MAP_SWIZZLE_128B,
          CU_TENSOR_MAP_L2_PROMOTION_L2_128B, CU_TENSOR_MAP_FLOAT_OOB_FILL_NONE);
}

extern "C" void kernel_launch(void* const* d_in, const int* in_sizes, int n_in,
                              void* d_out, int out_size)
{
    (void)in_sizes; (void)n_in; (void)out_size;

    const float* oV     = (const float*)d_in[0];
    const float* oT     = (const float*)d_in[1];
    const float* Wq_v_w = (const float*)d_in[2];
    const float* Wq_v_b = (const float*)d_in[3];
    const float* Wk_t_w = (const float*)d_in[4];
    const float* Wk_t_b = (const float*)d_in[5];
    const float* Wv_t_w = (const float*)d_in[6];
    const float* Wv_t_b = (const float*)d_in[7];
    const float* Wq_t_w = (const float*)d_in[8];
    const float* Wq_t_b = (const float*)d_in[9];
    const float* Wk_v_w = (const float*)d_in[10];
    const float* Wk_v_b = (const float*)d_in[11];
    const float* Wv_v_w = (const float*)d_in[12];
    const float* Wv_v_b = (const float*)d_in[13];
    const float* ffn1_w = (const float*)d_in[14];
    const float* ffn1_b = (const float*)d_in[15];
    const float* ffn2_w = (const float*)d_in[16];
    const float* ffn2_b = (const float*)d_in[17];

    float* out_vt = (float*)d_out;
    float* out_tv = out_vt + ELEM1;
    float* maskO  = out_vt + 2 * ELEM1;

    static float* scr = nullptr;
    if (!scr) cudaGetSymbolAddress((void**)&scr, g_scr);
    if (!g_enc) {
        void* p = nullptr;
        cudaDriverEntryPointQueryResult st;
        cudaGetDriverEntryPoint("cuTensorMapEncodeTiled", &p, cudaEnableDefault, &st);
        g_enc = (PFN_encodeTiled)p;
    }
    static cudaStream_t sA = nullptr;
    static cudaEvent_t evFork, evA;
    static bool init_done = false;
    if (!init_done) {
        cudaFuncSetAttribute(gemm_tc,   cudaFuncAttributeMaxDynamicSharedMemorySize, SMEM_DYN);
        cudaFuncSetAttribute(gemm_proj, cudaFuncAttributeMaxDynamicSharedMemorySize, SMEM_DYN);
        cudaStreamCreateWithFlags(&sA, cudaStreamNonBlocking);
        cudaEventCreateWithFlags(&evFork, cudaEventDisableTiming);
        cudaEventCreateWithFlags(&evA,    cudaEventDisableTiming);
        init_done = true;
    }

    float* Qv    = scr + 0 * ELEM1;
    float* Kt    = scr + 1 * ELEM1;
    float* VtT   = scr + 2 * ELEM1;   // (B, DT, SEQ)
    float* Qt    = scr + 3 * ELEM1;
    float* Kv    = scr + 4 * ELEM1;
    float* VvT   = scr + 5 * ELEM1;   // (B, DT, SEQ)
    float* Ssc   = scr + 6 * ELEM1;   // chain-4 scores
    float* maskT = scr + 7 * ELEM1;
    float* oVr   = scr + 8 * ELEM1;
    float* oTr   = scr + 9 * ELEM1;
    float* Ssc2  = scr + 10 * ELEM1;  // sim temp, then chain-5 scores
    float* Wr    = scr + 11 * ELEM1;
    float* poolV = Wr + 6L * DT * DT;
    float* poolT = poolV + BATCH * DT;
    float* lv    = poolT + BATCH * DT;
    float* partV = lv + 64;
    float* partT = partV + 8 * BATCH * 1024;
    float* biasV = partT + 8 * BATCH * 1024;
    float* biasT = biasV + 3072;

    const long N4BIG = ELEM1 / 4;
    const long S1 = (long)SEQ * SEQ;
    CUtensorMap tA, tB;
    const dim3 gw(24, 128, 1);
    const dim3 gb(8, 8, BATCH);

    // ===== serial prefix on stream 0 (identical to R11) =====
    round_kernel<<<2048, 256>>>((const float4*)oV, (float4*)oVr, N4BIG);
    round_kernel<<<2048, 256>>>((const float4*)oT, (float4*)oTr, N4BIG);
    Ptr6 wp;
    wp.in[0] = (const float4*)Wq_v_w;  wp.in[1] = (const float4*)Wk_v_w;
    wp.in[2] = (const float4*)Wv_v_w;  wp.in[3] = (const float4*)Wk_t_w;
    wp.in[4] = (const float4*)Wv_t_w;  wp.in[5] = (const float4*)Wq_t_w;
    round6_kernel<<<dim3(256, 6), 256>>>(wp, (float4*)Wr, (long)DT * DT / 4);
    cat_bias<<<12, 256>>>(Wq_v_b, Wk_v_b, Wv_v_b, biasV);
    cat_bias<<<12, 256>>>(Wk_t_b, Wv_t_b, Wq_t_b, biasT);

    pool1_kernel<<<dim3(4, BATCH, 8), 256>>>(oV, partV);
    pool1_kernel<<<dim3(4, BATCH, 8), 256>>>(oT, partT);
    pool2_kernel<<<dim3(4, BATCH), 256>>>(partV, poolV);
    pool2_kernel<<<dim3(4, BATCH), 256>>>(partT, poolT);
    ffn_kernel<<<BATCH, HID>>>(poolV, poolT, ffn1_w, ffn1_b, ffn2_w, ffn2_b, lv);

    enc3d(&tA, oVr, DT, BATCH * SEQ, 1);
    enc3d(&tB, Wr, DT, 3 * DT, 1);
    gemm_proj<<<gw, NTHR, SMEM_DYN>>>(tA, tB, Qv, Kv, VvT, biasV, 0b100u);

    enc3d(&tA, oTr, DT, BATCH * SEQ, 1);
    enc3d(&tB, Wr + 3L * DT * DT, DT, 3 * DT, 1);
    gemm_proj<<<gw, NTHR, SMEM_DYN>>>(tA, tB, Kt, VtT, Qt, biasT, 0b010u);

    enc3d(&tA, oVr, DT, SEQ, BATCH);
    enc3d(&tB, oTr, DT, SEQ, BATCH);
    gemm_tc<<<gb, NTHR, SMEM_DYN>>>(tA, tB, Ssc2, S1);
    mask_trans_kernel<<<dim3(BATCH, 32), 256>>>(Ssc2, lv, maskO, maskT);

    // ===== single fork: chain-4 on stream 0, chain-5 on sA =====
    cudaEventRecord(evFork, 0);
    cudaStreamWaitEvent(sA, evFork, 0);

    // chain 4 (V->T) on stream 0: Qv,Kt -> Ssc -> out_vt (reads maskO)
    enc3d(&tA, Qv, DT, SEQ, BATCH);
    enc3d(&tB, Kt, DT, SEQ, BATCH);
    gemm_tc<<<gb, NTHR, SMEM_DYN>>>(tA, tB, Ssc, S1);
    msoftmax_kernel<<<dim3(128, BATCH), 256>>>(Ssc, maskO);
    enc3d(&tA, Ssc, SEQ, SEQ, BATCH);
    enc3d(&tB, VtT, SEQ, DT, BATCH);
    gemm_tc<<<gb, NTHR, SMEM_DYN>>>(tA, tB, out_vt, S1);

    // chain 5 (T->V) on sA: Qt,Kv -> Ssc2 -> out_tv (reads maskT)
    enc3d(&tA, Qt, DT, SEQ, BATCH);
    enc3d(&tB, Kv, DT, SEQ, BATCH);
    gemm_tc<<<gb, NTHR, SMEM_DYN, sA>>>(tA, tB, Ssc2, S1);
    msoftmax_kernel<<<dim3(128, BATCH), 256, 0, sA>>>(Ssc2, maskT);
    enc3d(&tA, Ssc2, SEQ, SEQ, BATCH);
    enc3d(&tB, VvT, SEQ, DT, BATCH);
    gemm_tc<<<gb, NTHR, SMEM_DYN, sA>>>(tA, tB, out_tv, S1);

    // ===== join =====
    cudaEventRecord(evA, sA);
    cudaStreamWaitEvent(0, evA, 0);
}

// round 14
// speedup vs baseline: 1.4141x; 1.2992x over previous
#include <cuda_runtime.h>
#include <cuda.h>
#include <cstdint>

// ===========================================================================
#define BATCH 16
#define SEQ   1024
#define DT    1024
#define HID   512
#define NEG_INF_F (-1.0e9f)
static __device__ __host__ constexpr float INV_SQRT = 0.03125f;

static constexpr long ELEM1 = 16LL * 1024 * 1024;
__device__ __align__(1024) float g_scr[ELEM1 * 11 + 6L * DT * DT + 400000];

// ===========================================================================
// PTX helpers
// ===========================================================================
__device__ __forceinline__ uint32_t smem_u32(const void* p) {
    uint32_t a;
    asm("{ .reg .u64 t; cvta.to.shared.u64 t, %1; cvt.u32.u64 %0, t; }" : "=r"(a) : "l"(p));
    return a;
}
__device__ __forceinline__ uint32_t lds_u(uint32_t a) {
    uint32_t v;
    asm volatile("ld.shared.b32 %0, [%1];" : "=r"(v) : "r"(a));
    return v;
}
__device__ __forceinline__ float rnd_tf32(float f) {
    uint32_t r;
    asm volatile("cvt.rna.tf32.f32 %0, %1;" : "=r"(r) : "f"(f));
    return __uint_as_float(r);
}

#define MBARRIER_INIT(mbar, count) \
    asm volatile("mbarrier.init.shared.b64 [%0], %1;" :: "r"((uint32_t)(mbar)), "r"((uint32_t)(count)) : "memory")
#define MBARRIER_EXPECT_TX(mbar, bytes) \
    asm volatile("mbarrier.arrive.expect_tx.shared.b64 _, [%0], %1;" \
        :: "r"((uint32_t)(mbar)), "r"((uint32_t)(bytes)) : "memory")
#define MBARRIER_ARRIVE(mbar) \
    asm volatile("mbarrier.arrive.release.cta.shared.b64 _, [%0];" :: "r"((uint32_t)(mbar)) : "memory")
#define MBARRIER_WAIT_PARITY(mbar, parity) do {                                  \
    uint32_t _m = (uint32_t)(mbar);  uint32_t _p = (uint32_t)(parity);           \
    asm volatile(                                                                 \
        "{\n\t.reg .pred P1;\n\t"                                                 \
        "WL_%=:\n\t"                                                              \
        "mbarrier.try_wait.parity.acquire.cta.shared::cta.b64 P1, [%0], %1, 0x989680;\n\t" \
        "@P1 bra.uni WD_%=;\n\t"                                                  \
        "bra.uni WL_%=;\n\t"                                                      \
        "WD_%=:\n\t}"                                                             \
        :: "r"(_m), "r"(_p) : "memory");                                          \
} while (0)
#define TMA_LOAD_3D(saddr, tmap, cx, cy, cz, mbar) \
    asm volatile( \
        "cp.async.bulk.tensor.3d.shared::cta.global.tile.mbarrier::complete_tx::bytes " \
        "[%0], [%1, {%2, %3, %4}], [%5];" \
        :: "r"((uint32_t)(saddr)), "l"(tmap), "r"((int)(cx)), "r"((int)(cy)), "r"((int)(cz)), \
           "r"((uint32_t)(mbar)) : "memory")

// ===========================================================================
// GEMM config: CTA 128x128, KT=32/stage, 3 stages, 128 thr, 4 warps (64x64)
// ===========================================================================
static constexpr int BM = 128, BN = 128, KT = 32, STAGES = 3;
static constexpr int ABYT = BM * KT * 4;
static constexpr int BBYT = BN * KT * 4;
static constexpr int STB  = ABYT + BBYT;
static constexpr int SMEM_DYN = 1024 + STAGES * STB;   // 99328
static constexpr int NTHR = 128;

#define GEMM_MAINLOOP(tmA_, tmB_, zA_, zB_)                                         \
    if (tid == 0) {                                                                 \
        for (int s_ = 0; s_ < STAGES; s_++) {                                       \
            MBARRIER_INIT(FULLB(s_), 1);                                            \
            MBARRIER_INIT(EMPTYB(s_), 4);                                           \
        }                                                                           \
    }                                                                               \
    __syncthreads();                                                                \
    if (tid == 0) {                                                                 \
        for (int s_ = 0; s_ < STAGES; s_++) {                                       \
            MBARRIER_EXPECT_TX(FULLB(s_), STB);                                     \
            TMA_LOAD_3D(sb + s_ * STB,        &(tmA_), s_ * KT, m0, (zA_), FULLB(s_)); \
            TMA_LOAD_3D(sb + s_ * STB + ABYT, &(tmB_), s_ * KT, n0, (zB_), FULLB(s_)); \
        }                                                                           \
    }                                                                               \
    const uint32_t gx   = (uint32_t)gID << 4;                                       \
    const uint32_t rowA = (uint32_t)(wm * 64 + gID) * 128;                          \
    const uint32_t rowB = (uint32_t)(wn * 64 + gID) * 128;                          \
    int s = 0, ph = 0;                                                              \
    for (int kt = 0; kt < 32; kt++) {                                               \
        const uint32_t stg = sb + s * STB;                                          \
        MBARRIER_WAIT_PARITY(FULLB(s), ph);                                         \
        const uint32_t aBase = stg + rowA;                                          \
        const uint32_t bBase = stg + ABYT + rowB;                                   \
        _Pragma("unroll")                                                           \
        for (int kk = 0; kk < 4; kk++) {                                            \
            const uint32_t off0 = ((uint32_t)(kk * 32 + tig * 4)) ^ gx;             \
            const uint32_t off1 = off0 ^ 16u;                                       \
            uint32_t ua[4][4], ub[8][2];                                            \
            _Pragma("unroll")                                                       \
            for (int mi = 0; mi < 4; mi++) {                                        \
                ua[mi][0] = lds_u(aBase + mi * 2048 + off0);                        \
                ua[mi][1] = lds_u(aBase + mi * 2048 + 1024 + off0);                 \
                ua[mi][2] = lds_u(aBase + mi * 2048 + off1);                        \
                ua[mi][3] = lds_u(aBase + mi * 2048 + 1024 + off1);                 \
            }                                                                       \
            _Pragma("unroll")                                                       \
            for (int ni = 0; ni < 8; ni++) {                                        \
                ub[ni][0] = lds_u(bBase + ni * 1024 + off0);                        \
                ub[ni][1] = lds_u(bBase + ni * 1024 + off1);                        \
            }                                                                       \
            _Pragma("unroll")                                                       \
            for (int mi = 0; mi < 4; mi++)                                          \
                _Pragma("unroll")                                                   \
                for (int ni = 0; ni < 8; ni++)                                      \
                    asm volatile(                                                   \
                        "mma.sync.aligned.m16n8k8.row.col.f32.tf32.tf32.f32 "       \
                        "{%0,%1,%2,%3},{%4,%5,%6,%7},{%8,%9},{%0,%1,%2,%3};"        \
                        : "+f"(acc[mi][ni][0]), "+f"(acc[mi][ni][1]),               \
                          "+f"(acc[mi][ni][2]), "+f"(acc[mi][ni][3])                \
                        : "r"(ua[mi][0]), "r"(ua[mi][1]), "r"(ua[mi][2]), "r"(ua[mi][3]), \
                          "r"(ub[ni][0]), "r"(ub[ni][1]));                          \
        }                                                                           \
        __syncwarp();                                                               \
        if (lane == 0) MBARRIER_ARRIVE(EMPTYB(s));                                  \
        if (tid == 0 && kt + STAGES < 32) {                                         \
            MBARRIER_WAIT_PARITY(EMPTYB(s), ph);                                    \
            MBARRIER_EXPECT_TX(FULLB(s), STB);                                      \
            TMA_LOAD_3D(sb + s * STB,        &(tmA_), (kt + STAGES) * KT, m0, (zA_), FULLB(s)); \
            TMA_LOAD_3D(sb + s * STB + ABYT, &(tmB_), (kt + STAGES) * KT, n0, (zB_), FULLB(s)); \
        }                                                                           \
        if (++s == STAGES) { s = 0; ph ^= 1; }                                      \
    }                                                                               \
    __syncthreads();

// ===========================================================================
// Batched GEMM (no bias): C[z][M,N] = A[z] @ B[z]^T
// ===========================================================================
__global__ void __launch_bounds__(NTHR, 2)
gemm_tc(const __grid_constant__ CUtensorMap tmA,
        const __grid_constant__ CUtensorMap tmB,
        float* __restrict__ C, long sCz)
{
    extern __shared__ char dynraw[];
    __shared__ __align__(8) unsigned long long mb[2 * STAGES];
    uint32_t d0 = smem_u32(dynraw);
    uint32_t sb = (d0 + 1023u) & ~1023u;
    const int tid = threadIdx.x;
    const int warp = tid >> 5, lane = tid & 31;
    const int wm = warp & 1, wn = warp >> 1;
    const int gID = lane >> 2, tig = lane & 3;
    const int m0 = blockIdx.y * BM, n0 = blockIdx.x * BN, z = blockIdx.z;
    const uint32_t mbase = smem_u32(mb);
#define FULLB(s)  (mbase + 8 * (s))
#define EMPTYB(s) (mbase + 24 + 8 * (s))

    float acc[4][8][4];
#pragma unroll
    for (int mi = 0; mi < 4; mi++)
#pragma unroll
        for (int ni = 0; ni < 8; ni++)
#pragma unroll
            for (int e = 0; e < 4; e++) acc[mi][ni][e] = 0.0f;

    GEMM_MAINLOOP(tmA, tmB, z, z)

    float* ep = (float*)(dynraw + (sb - d0));
    const int P = 132;
#pragma unroll
    for (int mi = 0; mi < 4; mi++)
#pragma unroll
        for (int ni = 0; ni < 8; ni++) {
            const int r = wm * 64 + mi * 16 + gID;
            const int c = wn * 64 + ni * 8 + 2 * tig;
            *(float2*)(ep + r * P + c)       = make_float2(acc[mi][ni][0], acc[mi][ni][1]);
            *(float2*)(ep + (r + 8) * P + c) = make_float2(acc[mi][ni][2], acc[mi][ni][3]);
        }
    __syncthreads();
    float* Cz = C + (long)z * sCz;
#pragma unroll
    for (int it = 0; it < 32; it++) {
        const int idx = tid + it * NTHR;
        const int r = idx >> 5, c4 = (idx & 31) * 4;
        float4 v = *(float4*)(ep + r * P + c4);
        *(float4*)(Cz + (long)(m0 + r) * 1024 + n0 + c4) = v;
    }
#undef FULLB
#undef EMPTYB
}

// ===========================================================================
// Wide projection GEMM: C[M, 3072] = A[M,1024] @ W[3072,1024]^T + biasC
// ===========================================================================
__global__ void __launch_bounds__(NTHR, 2)
gemm_proj(const __grid_constant__ CUtensorMap tmA,
          const __grid_constant__ CUtensorMap tmB,
          float* __restrict__ p0, float* __restrict__ p1, float* __restrict__ p2,
          const float* __restrict__ biasC, uint32_t trans_mask)
{
    extern __shared__ char dynraw[];
    __shared__ __align__(8) unsigned long long mb[2 * STAGES];
    uint32_t d0 = smem_u32(dynraw);
    uint32_t sb = (d0 + 1023u) & ~1023u;
    const int tid = threadIdx.x;
    const int warp = tid >> 5, lane = tid & 31;
    const int wm = warp & 1, wn = warp >> 1;
    const int gID = lane >> 2, tig = lane & 3;
    const int m0 = blockIdx.y * BM, n0 = blockIdx.x * BN;
    const uint32_t mbase = smem_u32(mb);
#define FULLB(s)  (mbase + 8 * (s))
#define EMPTYB(s) (mbase + 24 + 8 * (s))

    float acc[4][8][4];
#pragma unroll
    for (int mi = 0; mi < 4; mi++)
#pragma unroll
        for (int ni = 0; ni < 8; ni++)
#pragma unroll
            for (int e = 0; e < 4; e++) acc[mi][ni][e] = 0.0f;

    GEMM_MAINLOOP(tmA, tmB, 0, 0)

    // bias + round
#pragma unroll
    for (int ni = 0; ni < 8; ni++) {
        const int nc = n0 + wn * 64 + ni * 8 + 2 * tig;
        const float b0 = __ldg(biasC + nc), b1 = __ldg(biasC + nc + 1);
#pragma unroll
        for (int mi = 0; mi < 4; mi++) {
            acc[mi][ni][0] = rnd_tf32(acc[mi][ni][0] + b0);
            acc[mi][ni][1] = rnd_tf32(acc[mi][ni][1] + b1);
            acc[mi][ni][2] = rnd_tf32(acc[mi][ni][2] + b0);
            acc[mi][ni][3] = rnd_tf32(acc[mi][ni][3] + b1);
        }
    }

    const int sec = n0 >> 10;
    const int n0l = n0 & 1023;
    float* dst = (sec == 0) ? p0 : (sec == 1) ? p1 : p2;
    const bool tr = (trans_mask >> sec) & 1u;
    float* ep = (float*)(dynraw + (sb - d0));

    if (!tr) {
        const int P = 132;
#pragma unroll
        for (int mi = 0; mi < 4; mi++)
#pragma unroll
            for (int ni = 0; ni < 8; ni++) {
                const int r = wm * 64 + mi * 16 + gID;
                const int c = wn * 64 + ni * 8 + 2 * tig;
                *(float2*)(ep + r * P + c)       = make_float2(acc[mi][ni][0], acc[mi][ni][1]);
                *(float2*)(ep + (r + 8) * P + c) = make_float2(acc[mi][ni][2], acc[mi][ni][3]);
            }
        __syncthreads();
#pragma unroll
        for (int it = 0; it < 32; it++) {
            const int idx = tid + it * NTHR;
            const int r = idx >> 5, c4 = (idx & 31) * 4;
            float4 v = *(float4*)(ep + r * P + c4);
            *(float4*)(dst + (long)(m0 + r) * 1024 + n0l + c4) = v;
        }
    } else {
        const int P = 129;
#pragma unroll
        for (int mi = 0; mi < 4; mi++)
#pragma unroll
            for (int ni = 0; ni < 8; ni++) {
                const int r = wm * 64 + mi * 16 + gID;
                const int c = wn * 64 + ni * 8 + 2 * tig;
                ep[r * P + c]           = acc[mi][ni][0];
                ep[r * P + c + 1]       = acc[mi][ni][1];
                ep[(r + 8) * P + c]     = acc[mi][ni][2];
                ep[(r + 8) * P + c + 1] = acc[mi][ni][3];
            }
        __syncthreads();
        const int b   = m0 >> 10;
        const int mlb = m0 & 1023;
#pragma unroll 8
        for (int it = 0; it < 128; it++) {
            const int idx = tid + it * NTHR;
            const int n = idx >> 7, m = idx & 127;
            dst[((long)b << 20) + (long)(n0l + n) * 1024 + (mlb + m)] = ep[m * P + n];
        }
    }
#undef FULLB
#undef EMPTYB
}

// ===========================================================================
// Pre-round to tf32
// ===========================================================================
__global__ void round_kernel(const float4* __restrict__ in, float4* __restrict__ out, long n4)
{
    long i = (long)blockIdx.x * blockDim.x + threadIdx.x;
    long stride = (long)gridDim.x * blockDim.x;
    for (; i < n4; i += stride) {
        float4 v = in[i];
        v.x = rnd_tf32(v.x); v.y = rnd_tf32(v.y);
        v.z = rnd_tf32(v.z); v.w = rnd_tf32(v.w);
        out[i] = v;
    }
}

struct Ptr6 { const float4* in[6]; };
__global__ void round6_kernel(Ptr6 p, float4* __restrict__ out, long n4each)
{
    const float4* in = p.in[blockIdx.y];
    float4* o = out + blockIdx.y * n4each;
    long i = (long)blockIdx.x * blockDim.x + threadIdx.x;
    long stride = (long)gridDim.x * blockDim.x;
    for (; i < n4each; i += stride) {
        float4 v = in[i];
        v.x = rnd_tf32(v.x); v.y = rnd_tf32(v.y);
        v.z = rnd_tf32(v.z); v.w = rnd_tf32(v.w);
        o[i] = v;
    }
}

__global__ void cat_bias(const float* __restrict__ a, const float* __restrict__ b,
                         const float* __restrict__ c, float* __restrict__ o)
{
    int i = blockIdx.x * 256 + threadIdx.x;
    o[i] = (i < 1024) ? a[i] : (i < 2048) ? b[i - 1024] : c[i - 2048];
}

// ===========================================================================
// Two-stage mean pool
// ===========================================================================
__global__ void pool1_kernel(const float* __restrict__ src, float* __restrict__ part)
{
    int b = blockIdx.y, sp = blockIdx.z;
    int d = blockIdx.x * 256 + threadIdx.x;
    const float* p = src + ((long)b << 20) + ((long)sp << 17) + d;
    float s = 0.f;
#pragma unroll 16
    for (int m = 0; m < 128; m++) s += p[m << 10];
    part[(((b << 3) + sp) << 10) + d] = s;
}
__global__ void pool2_kernel(const float* __restrict__ part, float* __restrict__ dst)
{
    int b = blockIdx.y;
    int d = blockIdx.x * 256 + threadIdx.x;
    float s = 0.f;
#pragma unroll
    for (int sp = 0; sp < 8; sp++) s += part[(((b << 3) + sp) << 10) + d];
    dst[(b << 10) + d] = s * (1.0f / 1024.0f);
}

// ===========================================================================
// Gate FFN
// ===========================================================================
__global__ void ffn_kernel(const float* __restrict__ poolV, const float* __restrict__ poolT,
                           const float* __restrict__ w1, const float* __restrict__ b1,
                           const float* __restrict__ w2, const float* __restrict__ b2,
                           float* __restrict__ lout)
{
    __shared__ float x[2 * DT];
    __shared__ float red[HID];
    int b = blockIdx.x, t = threadIdx.x;
    for (int i = t; i < 2 * DT; i += HID)
        x[i] = (i < DT) ? poolV[b * DT + i] : poolT[b * DT + (i - DT)];
    __syncthreads();
    float acc = b1[t];
    const float* wr = w1 + (long)t * (2 * DT);
#pragma unroll 8
    for (int k = 0; k < 2 * DT; k++) acc += wr[k] * x[k];
    float h = fmaxf(acc, 0.0f);
    red[t] = h * w2[t];
    __syncthreads();
    for (int s = HID / 2; s > 0; s >>= 1) {
        if (t < s) red[t] += red[t + s];
        __syncthreads();
    }
    if (t == 0) lout[b] = 1.0f / (1.0f + expf(-(red[0] + b2[0])));
}

// ===========================================================================
// Warp reductions
// ===========================================================================
__device__ __forceinline__ float warp_max(float v)
{
#pragma unroll
    for (int o = 16; o > 0; o >>= 1)
        v = fmaxf(v, __shfl_xor_sync(0xFFFFFFFFu, v, o));
    return v;
}
__device__ __forceinline__ float warp_sum(float v)
{
#pragma unroll
    for (int o = 16; o > 0; o >>= 1)
        v += __shfl_xor_sync(0xFFFFFFFFu, v, o);
    return v;
}

// ===========================================================================
// Fused mask + transpose
// ===========================================================================
__global__ void mask_trans_kernel(const float* __restrict__ S, const float* __restrict__ lv,
                                  float* __restrict__ maskO, float* __restrict__ maskT)
{
    __shared__ unsigned char tile[32][1028];
    const int b = blockIdx.x;
    const int m0g = blockIdx.y * 32;
    const int wid = threadIdx.x >> 5, lane = threadIdx.x & 31;
    const float l = lv[b];
    const long base = (long)b << 20;

    for (int rp = 0; rp < 4; rp++) {
        const int rl = rp * 8 + wid;
        const float4* p4 = (const float4*)(S + base + (long)(m0g + rl) * 1024);
        float4 x[8];
        float mx = -3.4e38f;
#pragma unroll
        for (int i = 0; i < 8; i++) {
            float4 v = p4[lane + i * 32];
            v.x *= INV_SQRT; v.y *= INV_SQRT; v.z *= INV_SQRT; v.w *= INV_SQRT;
            x[i] = v;
            mx = fmaxf(mx, fmaxf(fmaxf(v.x, v.y), fmaxf(v.z, v.w)));
        }
        mx = warp_max(mx);
        float ssum = 0.f;
        float4 e[8];
#pragma unroll
        for (int i = 0; i < 8; i++) {
            e[i].x = expf(x[i].x - mx); e[i].y = expf(x[i].y - mx);
            e[i].z = expf(x[i].z - mx); e[i].w = expf(x[i].w - mx);
            ssum += e[i].x + e[i].y + e[i].z + e[i].w;
        }
        ssum = warp_sum(ssum);
        const float thr = l * ssum;
        float4* o4 = (float4*)(maskO + base + (long)(m0g + rl) * 1024);
#pragma unroll
        for (int i = 0; i < 8; i++) {
            float4 mv;
            mv.x = (e[i].x >= thr) ? 1.0f : 0.0f;
            mv.y = (e[i].y >= thr) ? 1.0f : 0.0f;
            mv.z = (e[i].z >= thr) ? 1.0f : 0.0f;
            mv.w = (e[i].w >= thr) ? 1.0f : 0.0f;
            o4[lane + i * 32] = mv;
            uchar4 mb4 = make_uchar4((unsigned char)mv.x, (unsigned char)mv.y,
                                     (unsigned char)mv.z, (unsigned char)mv.w);
            *(uchar4*)&tile[rl][4 * (lane + i * 32)] = mb4;
        }
    }
    __syncthreads();
    for (int it = 0; it < 32; it++) {
        const int idx = threadIdx.x + it * 256;
        const int n = idx >> 3, mq = (idx & 7) * 4;
        float4 v;
        v.x = (float)tile[mq + 0][n];
        v.y = (float)tile[mq + 1][n];
        v.z = (float)tile[mq + 2][n];
        v.w = (float)tile[mq + 3][n];
        *(float4*)(maskT + base + (long)n * 1024 + m0g + mq) = v;
    }
}

// ===========================================================================
// Masked softmax, warp-per-row, in place; outputs rounded to tf32.
// ===========================================================================
__global__ void msoftmax_kernel(float* __restrict__ S, const float* __restrict__ maskM)
{
    const int b = blockIdx.y;
    const int row = blockIdx.x * 8 + (threadIdx.x >> 5);
    const int lane = threadIdx.x & 31;
    const long base = ((long)b << 20) + (long)row * 1024;
    float4* p4 = (float4*)(S + base);
    const float4* mk4 = (const float4*)(maskM + base);

    float4 x[8];
    float mx = -3.4e38f;
#pragma unroll
    for (int i = 0; i < 8; i++) {
        float4 v = p4[lane + i * 32];
        float4 m = mk4[lane + i * 32];
        v.x = (m.x != 0.0f) ? v.x * INV_SQRT : NEG_INF_F;
        v.y = (m.y != 0.0f) ? v.y * INV_SQRT : NEG_INF_F;
        v.z = (m.z != 0.0f) ? v.z * INV_SQRT : NEG_INF_F;
        v.w = (m.w != 0.0f) ? v.w * INV_SQRT : NEG_INF_F;
        x[i] = v;
        mx = fmaxf(mx, fmaxf(fmaxf(v.x, v.y), fmaxf(v.z, v.w)));
    }
    mx = warp_max(mx);
    float ssum = 0.f;
#pragma unroll
    for (int i = 0; i < 8; i++) {
        x[i].x = expf(x[i].x - mx); x[i].y = expf(x[i].y - mx);
        x[i].z = expf(x[i].z - mx); x[i].w = expf(x[i].w - mx);
        ssum += x[i].x + x[i].y + x[i].z + x[i].w;
    }
    ssum = warp_sum(ssum);
    const float inv = 1.0f / ssum;
#pragma unroll
    for (int i = 0; i < 8; i++) {
        float4 v;
        v.x = rnd_tf32(x[i].x * inv); v.y = rnd_tf32(x[i].y * inv);
        v.z = rnd_tf32(x[i].z * inv); v.w = rnd_tf32(x[i].w * inv);
        p4[lane + i * 32] = v;
    }
}

// ===========================================================================
// Host side
// ===========================================================================
typedef CUresult (*PFN_encodeTiled)(CUtensorMap*, CUtensorMapDataType, cuuint32_t, void*,
                                    const cuuint64_t*, const cuuint64_t*, const cuuint32_t*,
                                    const cuuint32_t*, CUtensorMapInterleave, CUtensorMapSwizzle,
                                    CUtensorMapL2promotion, CUtensorMapFloatOOBfill);
static PFN_encodeTiled g_enc = nullptr;

static void enc3d(CUtensorMap* tm, const void* p, long K, long R, long Z)
{
    cuuint64_t dims[3] = {(cuuint64_t)K, (cuuint64_t)R, (cuuint64_t)Z};
    cuuint64_t str[2]  = {(cuuint64_t)(K * 4), (cuuint64_t)(K * R * 4)};
    cuuint32_t box[3]  = {(cuuint32_t)KT, 128, 1};
    cuuint32_t es[3]   = {1, 1, 1};
    g_enc(tm, CU_TENSOR_MAP_DATA_TYPE_FLOAT32, 3, (void*)p, dims, str, box, es,
          CU_TENSOR_MAP_INTERLEAVE_NONE, CU_TENSOR_MAP_SWIZZLE_128B,
          CU_TENSOR_MAP_L2_PROMOTION_L2_128B, CU_TENSOR_MAP_FLOAT_OOB_FILL_NONE);
}

extern "C" void kernel_launch(void* const* d_in, const int* in_sizes, int n_in,
                              void* d_out, int out_size)
{
    (void)in_sizes; (void)n_in; (void)out_size;

    const float* oV     = (const float*)d_in[0];
    const float* oT     = (const float*)d_in[1];
    const float* Wq_v_w = (const float*)d_in[2];
    const float* Wq_v_b = (const float*)d_in[3];
    const float* Wk_t_w = (const float*)d_in[4];
    const float* Wk_t_b = (const float*)d_in[5];
    const float* Wv_t_w = (const float*)d_in[6];
    const float* Wv_t_b = (const float*)d_in[7];
    const float* Wq_t_w = (const float*)d_in[8];
    const float* Wq_t_b = (const float*)d_in[9];
    const float* Wk_v_w = (const float*)d_in[10];
    const float* Wk_v_b = (const float*)d_in[11];
    const float* Wv_v_w = (const float*)d_in[12];
    const float* Wv_v_b = (const float*)d_in[13];
    const float* ffn1_w = (const float*)d_in[14];
    const float* ffn1_b = (const float*)d_in[15];
    const float* ffn2_w = (const float*)d_in[16];
    const float* ffn2_b = (const float*)d_in[17];

    float* out_vt = (float*)d_out;
    float* out_tv = out_vt + ELEM1;
    float* maskO  = out_vt + 2 * ELEM1;

    static float* scr = nullptr;
    if (!scr) cudaGetSymbolAddress((void**)&scr, g_scr);
    if (!g_enc) {
        void* p = nullptr;
        cudaDriverEntryPointQueryResult st;
        cudaGetDriverEntryPoint("cuTensorMapEncodeTiled", &p, cudaEnableDefault, &st);
        g_enc = (PFN_encodeTiled)p;
    }
    static cudaStream_t sA = nullptr;
    static cudaEvent_t evFork, evR, evPT, evM, evA;
    static bool init_done = false;
    if (!init_done) {
        cudaFuncSetAttribute(gemm_tc,   cudaFuncAttributeMaxDynamicSharedMemorySize, SMEM_DYN);
        cudaFuncSetAttribute(gemm_proj, cudaFuncAttributeMaxDynamicSharedMemorySize, SMEM_DYN);
        cudaStreamCreateWithFlags(&sA, cudaStreamNonBlocking);
        cudaEventCreateWithFlags(&evFork, cudaEventDisableTiming);
        cudaEventCreateWithFlags(&evR,    cudaEventDisableTiming);
        cudaEventCreateWithFlags(&evPT,   cudaEventDisableTiming);
        cudaEventCreateWithFlags(&evM,    cudaEventDisableTiming);
        cudaEventCreateWithFlags(&evA,    cudaEventDisableTiming);
        init_done = true;
    }

    float* Qv    = scr + 0 * ELEM1;
    float* Kt    = scr + 1 * ELEM1;
    float* VtT   = scr + 2 * ELEM1;   // (B, DT, SEQ)
    float* Qt    = scr + 3 * ELEM1;
    float* Kv    = scr + 4 * ELEM1;
    float* VvT   = scr + 5 * ELEM1;   // (B, DT, SEQ)
    float* Ssc   = scr + 6 * ELEM1;   // chain-4 scores
    float* maskT = scr + 7 * ELEM1;
    float* oVr   = scr + 8 * ELEM1;
    float* oTr   = scr + 9 * ELEM1;
    float* Ssc2  = scr + 10 * ELEM1;  // sim temp, then chain-5 scores
    float* Wr    = scr + 11 * ELEM1;
    float* poolV = Wr + 6L * DT * DT;
    float* poolT = poolV + BATCH * DT;
    float* lv    = poolT + BATCH * DT;
    float* partV = lv + 64;
    float* partT = partV + 8 * BATCH * 1024;
    float* biasV = partT + 8 * BATCH * 1024;
    float* biasT = biasV + 3072;

    const long N4BIG = ELEM1 / 4;
    const long S1 = (long)SEQ * SEQ;
    CUtensorMap tA, tB;
    const dim3 gw(24, 128, 1);
    const dim3 gb(8, 8, BATCH);

    // ===== fork at entry: sA does pools+ffn (independent of rounds) =====
    cudaEventRecord(evFork, 0);
    cudaStreamWaitEvent(sA, evFork, 0);

    pool1_kernel<<<dim3(4, BATCH, 8), 256, 0, sA>>>(oV, partV);
    pool1_kernel<<<dim3(4, BATCH, 8), 256, 0, sA>>>(oT, partT);
    pool2_kernel<<<dim3(4, BATCH), 256, 0, sA>>>(partV, poolV);
    pool2_kernel<<<dim3(4, BATCH), 256, 0, sA>>>(partT, poolT);
    ffn_kernel<<<BATCH, HID, 0, sA>>>(poolV, poolT, ffn1_w, ffn1_b, ffn2_w, ffn2_b, lv);

    // ===== s0: rounds + weight prep =====
    round_kernel<<<2048, 256>>>((const float4*)oV, (float4*)oVr, N4BIG);
    round_kernel<<<2048, 256>>>((const float4*)oT, (float4*)oTr, N4BIG);
    Ptr6 wp;
    wp.in[0] = (const float4*)Wq_v_w;  wp.in[1] = (const float4*)Wk_v_w;
    wp.in[2] = (const float4*)Wv_v_w;  wp.in[3] = (const float4*)Wk_t_w;
    wp.in[4] = (const float4*)Wv_t_w;  wp.in[5] = (const float4*)Wq_t_w;
    round6_kernel<<<dim3(256, 6), 256>>>(wp, (float4*)Wr, (long)DT * DT / 4);
    cat_bias<<<12, 256>>>(Wq_v_b, Wk_v_b, Wv_v_b, biasV);
    cat_bias<<<12, 256>>>(Wk_t_b, Wv_t_b, Wq_t_b, biasT);
    cudaEventRecord(evR, 0);          // oVr, oTr, Wr, biasV, biasT ready

    // ===== sA: projT (after ffn, after evR) =====
    cudaStreamWaitEvent(sA, evR, 0);
    enc3d(&tA, oTr, DT, BATCH * SEQ, 1);
    enc3d(&tB, Wr + 3L * DT * DT, DT, 3 * DT, 1);
    gemm_proj<<<gw, NTHR, SMEM_DYN, sA>>>(tA, tB, Kt, VtT, Qt, biasT, 0b010u);
    cudaEventRecord(evPT, sA);        // Kt, VtT, Qt, (and transitively lv) ready

    // ===== s0: projV + sim =====
    enc3d(&tA, oVr, DT, BATCH * SEQ, 1);
    enc3d(&tB, Wr, DT, 3 * DT, 1);
    gemm_proj<<<gw, NTHR, SMEM_DYN>>>(tA, tB, Qv, Kv, VvT, biasV, 0b100u);

    enc3d(&tA, oVr, DT, SEQ, BATCH);
    enc3d(&tB, oTr, DT, SEQ, BATCH);
    gemm_tc<<<gb, NTHR, SMEM_DYN>>>(tA, tB, Ssc2, S1);

    // ===== s0: mask (needs lv from sA + sim; evPT covers lv and projT) =====
    cudaStreamWaitEvent(0, evPT, 0);
    mask_trans_kernel<<<dim3(BATCH, 32), 256>>>(Ssc2, lv, maskO, maskT);
    cudaEventRecord(evM, 0);          // masks + (transitively) projV ready

    // ===== chain 4 (V->T) on s0: Qv,Kt -> Ssc -> out_vt =====
    enc3d(&tA, Qv, DT, SEQ, BATCH);
    enc3d(&tB, Kt, DT, SEQ, BATCH);
    gemm_tc<<<gb, NTHR, SMEM_DYN>>>(tA, tB, Ssc, S1);
    msoftmax_kernel<<<dim3(128, BATCH), 256>>>(Ssc, maskO);
    enc3d(&tA, Ssc, SEQ, SEQ, BATCH);
    enc3d(&tB, VtT, SEQ, DT, BATCH);
    gemm_tc<<<gb, NTHR, SMEM_DYN>>>(tA, tB, out_vt, S1);

    // ===== chain 5 (T->V) on sA: Qt,Kv -> Ssc2 -> out_tv =====
    cudaStreamWaitEvent(sA, evM, 0);  // covers Kv/VvT (projV) + maskT + Ssc2 free
    enc3d(&tA, Qt, DT, SEQ, BATCH);
    enc3d(&tB, Kv, DT, SEQ, BATCH);
    gemm_tc<<<gb, NTHR, SMEM_DYN, sA>>>(tA, tB, Ssc2, S1);
    msoftmax_kernel<<<dim3(128, BATCH), 256, 0, sA>>>(Ssc2, maskT);
    enc3d(&tA, Ssc2, SEQ, SEQ, BATCH);
    enc3d(&tB, VvT, SEQ, DT, BATCH);
    gemm_tc<<<gb, NTHR, SMEM_DYN, sA>>>(tA, tB, out_tv, S1);

    // ===== join =====
    cudaEventRecord(evA, sA);
    cudaStreamWaitEvent(0, evA, 0);
}